// round 5
// baseline (speedup 1.0000x reference)
#include <cuda_runtime.h>
#include <cuda_bf16.h>
#include <mma.h>
#include <math.h>
#include <cstdint>

using namespace nvcuda;

// ---------------- problem constants ----------------
#define BB   256      // batch
#define CC   256      // channels
#define NN   196      // tokens (14*14)
#define NH   8        // heads
#define DD   32       // head dim
#define CM   2048     // ffn hidden
#define MROWS (BB*NN) // 50176
#define EPSBN 1e-5f

// ---------------- scratch (device globals; no allocations allowed) ----------------
__device__ float g_t [(size_t)MROWS*CC];      // tokens [B*N, C]
__device__ float g_qkv[(size_t)3*BB*NH*NN*DD]; // [part, b, h, n, d]
__device__ float g_o [(size_t)MROWS*CC];      // attention out [B*N, C]
__device__ float g_t2[(size_t)MROWS*CC];      // after repbn1
__device__ float g_h [(size_t)MROWS*CM];      // ffn hidden
__device__ float g_t3[(size_t)MROWS*CC];      // before final transpose

// ---------------- cp.async helpers ----------------
__device__ __forceinline__ void cp_async16(void* smem_dst, const void* gsrc)
{
    unsigned int s = (unsigned int)__cvta_generic_to_shared(smem_dst);
    asm volatile("cp.async.cg.shared.global [%0], [%1], 16;\n" :: "r"(s), "l"(gsrc));
}
__device__ __forceinline__ void cp_commit() { asm volatile("cp.async.commit_group;\n"); }
template <int N>
__device__ __forceinline__ void cp_wait() { asm volatile("cp.async.wait_group %0;\n" :: "n"(N)); }

// ---------------- transposes ----------------
__global__ void transpose_in(const float* __restrict__ x, float* __restrict__ t)
{
    __shared__ float tile[32][33];
    int b  = blockIdx.z;
    int n0 = blockIdx.x * 32;
    int c0 = blockIdx.y * 32;
    int tx = threadIdx.x, ty = threadIdx.y;
#pragma unroll
    for (int i = 0; i < 4; i++) {
        int c = c0 + ty + 8*i;
        int n = n0 + tx;
        if (n < NN) tile[ty + 8*i][tx] = x[((size_t)b*CC + c)*NN + n];
    }
    __syncthreads();
#pragma unroll
    for (int i = 0; i < 4; i++) {
        int n = n0 + ty + 8*i;
        int c = c0 + tx;
        if (n < NN) t[((size_t)b*NN + n)*CC + c] = tile[tx][ty + 8*i];
    }
}

__global__ void transpose_out(const float* __restrict__ t, float* __restrict__ x)
{
    __shared__ float tile[32][33];
    int b  = blockIdx.z;
    int n0 = blockIdx.x * 32;
    int c0 = blockIdx.y * 32;
    int tx = threadIdx.x, ty = threadIdx.y;
#pragma unroll
    for (int i = 0; i < 4; i++) {
        int n = n0 + ty + 8*i;
        int c = c0 + tx;
        if (n < NN) tile[ty + 8*i][tx] = t[((size_t)b*NN + n)*CC + c];
    }
    __syncthreads();
#pragma unroll
    for (int i = 0; i < 4; i++) {
        int c = c0 + ty + 8*i;
        int n = n0 + tx;
        if (n < NN) x[((size_t)b*CC + c)*NN + n] = tile[tx][ty + 8*i];
    }
}

// ---------------- epilogue params ----------------
struct EpiParams {
    const float* bias;
    const float* resid;
    const float* gamma;
    const float* beta;
    const float* rm;
    const float* rv;
    const float* alpha;  // scalar
    const float* saw;    // [B]
    const float* sab;    // [B]
    float*       out;
};

// EPI 0: qkv scatter  | EPI 1: proj + repbn1 | EPI 2: b1 + SpatialSILU | EPI 3: b2 + repbn2
template <int EPI>
__device__ __forceinline__ void apply_epi(int r, int c, float val, const EpiParams& p)
{
    if constexpr (EPI == 0) {
        val += p.bias[c];
        int part = c >> 8;
        int cc   = c & 255;
        int head = cc >> 5;
        int d    = cc & 31;
        int b    = r / NN;
        int n    = r - b * NN;
        size_t PS = (size_t)BB*NH*NN*DD;
        p.out[(size_t)part*PS + (((size_t)(b*NH + head))*NN + n)*DD + d] = val;
    } else if constexpr (EPI == 1 || EPI == 3) {
        val += p.bias[c];
        float tv = p.resid[(size_t)r*CC + c];
        float s  = p.gamma[c] * rsqrtf(p.rv[c] + EPSBN);
        float a  = p.alpha[0];
        float u  = tv + val;
        p.out[(size_t)r*CC + c] = u * (s + a) + (p.beta[c] - p.rm[c]*s);
    } else { // EPI == 2
        val += p.bias[c];
        int b = r / NN;
        float w  = p.saw[b];
        float sb = p.sab[b];
        float wg = w * val + sb;
        float sg = 1.0f / (1.0f + __expf(-wg * val));
        p.out[(size_t)r*CM + c] = val * sg;
    }
}

// ---------------- TF32 tiled GEMM, cp.async 2-stage pipelined ----------------
// block tile 128x128, K-step 32, 8 warps (2x4 wmma tiles of 16x16 per warp)
// dynamic smem: As[2][128][36] | Bs[2][32][132] | stage[8][256]
// NOTE: no explicit __float_to_tf32 — the tf32 HMMA datapath ignores low
// mantissa bits (truncation), saving 24 ALU ops per kk-step on the critical path.
#define AS_STRIDE 36
#define BS_STRIDE 132
#define AS_FLOATS (128*AS_STRIDE)
#define BS_FLOATS (32*BS_STRIDE)
#define GEMM_SMEM_FLOATS (2*AS_FLOATS + 2*BS_FLOATS + 8*256)

template <int EPI>
__global__ __launch_bounds__(256, 2)
void gemm_tf32(const float* __restrict__ A, const float* __restrict__ Bm,
               int M, int N, int K, EpiParams p)
{
    extern __shared__ float sm[];
    float* As  = sm;                       // [2][128][36]
    float* Bs  = sm + 2*AS_FLOATS;         // [2][32][132]
    float* stg = sm + 2*AS_FLOATS + 2*BS_FLOATS; // [8][256]

    int tid  = threadIdx.x;
    int warp = tid >> 5;
    int lane = tid & 31;
    int wm   = warp >> 1;   // 0..3
    int wn   = warp & 1;    // 0..1
    int bn   = blockIdx.x;
    int bm   = blockIdx.y;
    size_t arow0 = (size_t)bm * 128;

    wmma::fragment<wmma::accumulator, 16, 16, 8, float> acc[2][4];
#pragma unroll
    for (int i = 0; i < 2; i++)
#pragma unroll
        for (int j = 0; j < 4; j++)
            wmma::fill_fragment(acc[i][j], 0.0f);

    // load-thread mapping
    int ar  = tid >> 3;          // 0..31  (A row within group of 32)
    int ac4 = (tid & 7) * 4;     // 0,4,...,28
    int br  = tid >> 5;          // 0..7   (B row within group of 8)
    int bc4 = (tid & 31) * 4;    // 0..124

    const float* Abase = A + arow0 * (size_t)K;
    const float* Bbase = Bm + (size_t)bn * 128;

    // async tile loader
    auto load_tile = [&](int stage, int k0) {
        float* Ad = As + stage * AS_FLOATS;
        float* Bd = Bs + stage * BS_FLOATS;
#pragma unroll
        for (int it = 0; it < 4; it++) {
            int row = ar + it*32;
            cp_async16(&Ad[row*AS_STRIDE + ac4], &Abase[(size_t)row*K + k0 + ac4]);
        }
#pragma unroll
        for (int it = 0; it < 4; it++) {
            int row = br + it*8;
            cp_async16(&Bd[row*BS_STRIDE + bc4], &Bbase[(size_t)(k0 + row)*N + bc4]);
        }
        cp_commit();
    };

    int ntiles = K >> 5;
    load_tile(0, 0);

    for (int t = 0; t < ntiles; t++) {
        int cur = t & 1;
        if (t + 1 < ntiles) {
            load_tile((t + 1) & 1, (t + 1) << 5);
            cp_wait<1>();
        } else {
            cp_wait<0>();
        }
        __syncthreads();

        float* Ac = As + cur * AS_FLOATS;
        float* Bc = Bs + cur * BS_FLOATS;
#pragma unroll
        for (int kk = 0; kk < 32; kk += 8) {
            wmma::fragment<wmma::matrix_a, 16, 16, 8, wmma::precision::tf32, wmma::row_major> af[2];
            wmma::fragment<wmma::matrix_b, 16, 16, 8, wmma::precision::tf32, wmma::row_major> bf[4];
#pragma unroll
            for (int i = 0; i < 2; i++)
                wmma::load_matrix_sync(af[i], &Ac[(wm*32 + i*16)*AS_STRIDE + kk], AS_STRIDE);
#pragma unroll
            for (int j = 0; j < 4; j++)
                wmma::load_matrix_sync(bf[j], &Bc[kk*BS_STRIDE + wn*64 + j*16], BS_STRIDE);
#pragma unroll
            for (int i = 0; i < 2; i++)
#pragma unroll
                for (int j = 0; j < 4; j++)
                    wmma::mma_sync(acc[i][j], af[i], bf[j], acc[i][j]);
        }
        __syncthreads();
    }

    // epilogue via per-warp staging
    float* stw = stg + warp * 256;
#pragma unroll
    for (int i = 0; i < 2; i++) {
#pragma unroll
        for (int j = 0; j < 4; j++) {
            wmma::store_matrix_sync(stw, acc[i][j], 16, wmma::mem_row_major);
            __syncwarp();
            int r0 = bm*128 + wm*32 + i*16;
            int c0 = bn*128 + wn*64 + j*16;
#pragma unroll
            for (int q = 0; q < 8; q++) {
                int e  = lane*8 + q;
                int rr = e >> 4;
                int cc = e & 15;
                apply_epi<EPI>(r0 + rr, c0 + cc, stw[e], p);
            }
            __syncwarp();
        }
    }
}

// ---------------- attention: one block per (b, head) ----------------
// smem: kst[32][196] (K transposed), vs[196][32], qs[8][4][32], ps[8][196][4]
#define ATTN_SMEM_FLOATS (32*196 + 196*32 + 8*4*32 + 8*196*4)

__global__ __launch_bounds__(256)
void attn_kernel(const float* __restrict__ qkv, float* __restrict__ o)
{
    extern __shared__ float sm[];
    float* kst = sm;                    // [d][j]  d*196 + j
    float* vs  = sm + 32*196;           // [j][d]  j*32 + d
    float* qs  = sm + 2*32*196;         // [w][4][32]
    float* ps  = qs + 8*4*32;           // [w][196][4]

    int bh = blockIdx.x;
    int b  = bh >> 3;
    int h  = bh & 7;
    int tid  = threadIdx.x;
    int w    = tid >> 5;
    int lane = tid & 31;

    size_t PS = (size_t)BB*NH*NN*DD;
    const float* qp = qkv + ((size_t)(b*NH + h))*NN*DD;
    const float* kp = qp + PS;
    const float* vp = qp + 2*PS;

    // load K transposed + V straight
    for (int idx = tid; idx < NN*DD; idx += 256) {
        int j = idx >> 5;
        int d = idx & 31;
        float kv = kp[idx];
        kst[d*NN + j] = kv;
        vs[idx] = vp[idx];
    }
    __syncthreads();

    const float scale = 0.1767766952966369f; // 32^-0.5
    float* qsw = qs + w*128;
    float* psw = ps + w*784;

    int jidx[7]; bool jok[7];
#pragma unroll
    for (int jj = 0; jj < 7; jj++) { jidx[jj] = lane + 32*jj; jok[jj] = jidx[jj] < NN; }

    for (int g = w; g < 49; g += 8) {
        int r0 = g * 4;
#pragma unroll
        for (int t = 0; t < 4; t++)
            qsw[t*32 + lane] = qp[(size_t)(r0 + t)*DD + lane];
        __syncwarp();

        float s[7][4];
#pragma unroll
        for (int jj = 0; jj < 7; jj++)
#pragma unroll
            for (int r = 0; r < 4; r++) s[jj][r] = 0.0f;

        for (int d = 0; d < 32; d++) {
            float qv0 = qsw[0*32 + d];
            float qv1 = qsw[1*32 + d];
            float qv2 = qsw[2*32 + d];
            float qv3 = qsw[3*32 + d];
            const float* krow = &kst[d*NN];
#pragma unroll
            for (int jj = 0; jj < 7; jj++) {
                float kv = jok[jj] ? krow[jidx[jj]] : 0.0f;
                s[jj][0] += qv0 * kv;
                s[jj][1] += qv1 * kv;
                s[jj][2] += qv2 * kv;
                s[jj][3] += qv3 * kv;
            }
        }

#pragma unroll
        for (int r = 0; r < 4; r++) {
            float mx = -INFINITY;
#pragma unroll
            for (int jj = 0; jj < 7; jj++) {
                float sv = jok[jj] ? s[jj][r] * scale : -INFINITY;
                s[jj][r] = sv;
                mx = fmaxf(mx, sv);
            }
#pragma unroll
            for (int off = 16; off > 0; off >>= 1)
                mx = fmaxf(mx, __shfl_xor_sync(0xFFFFFFFFu, mx, off));
            float sum = 0.0f;
#pragma unroll
            for (int jj = 0; jj < 7; jj++) {
                float e = jok[jj] ? __expf(s[jj][r] - mx) : 0.0f;
                s[jj][r] = e;
                sum += e;
            }
#pragma unroll
            for (int off = 16; off > 0; off >>= 1)
                sum += __shfl_xor_sync(0xFFFFFFFFu, sum, off);
            float inv = 1.0f / sum;
#pragma unroll
            for (int jj = 0; jj < 7; jj++)
                if (jok[jj]) psw[jidx[jj]*4 + r] = s[jj][r] * inv;
        }
        __syncwarp();

        float a0 = 0.f, a1 = 0.f, a2 = 0.f, a3 = 0.f;
#pragma unroll 4
        for (int j = 0; j < NN; j++) {
            float4 pv = *(const float4*)&psw[j*4];
            float vv = vs[j*32 + lane];
            a0 += pv.x * vv;
            a1 += pv.y * vv;
            a2 += pv.z * vv;
            a3 += pv.w * vv;
        }
        size_t ob = ((size_t)b*NN + r0)*CC + h*DD + lane;
        o[ob + 0*CC] = a0;
        o[ob + 1*CC] = a1;
        o[ob + 2*CC] = a2;
        o[ob + 3*CC] = a3;
        __syncwarp();
    }
}

// ---------------- launch ----------------
extern "C" void kernel_launch(void* const* d_in, const int* in_sizes, int n_in,
                              void* d_out, int out_size)
{
    const float* x      = (const float*)d_in[0];
    const float* W_qkv  = (const float*)d_in[1];
    const float* b_qkv  = (const float*)d_in[2];
    const float* W_proj = (const float*)d_in[3];
    const float* b_proj = (const float*)d_in[4];
    const float* W1     = (const float*)d_in[5];
    const float* b1     = (const float*)d_in[6];
    const float* W2     = (const float*)d_in[7];
    const float* b2     = (const float*)d_in[8];
    const float* sa_w   = (const float*)d_in[9];
    const float* sa_b   = (const float*)d_in[10];
    const float* alpha1 = (const float*)d_in[11];
    const float* gamma1 = (const float*)d_in[12];
    const float* beta1  = (const float*)d_in[13];
    const float* rm1    = (const float*)d_in[14];
    const float* rv1    = (const float*)d_in[15];
    const float* alpha2 = (const float*)d_in[16];
    const float* gamma2 = (const float*)d_in[17];
    const float* beta2  = (const float*)d_in[18];
    const float* rm2    = (const float*)d_in[19];
    const float* rv2    = (const float*)d_in[20];
    float* out = (float*)d_out;

    float *t_p, *qkv_p, *o_p, *t2_p, *h_p, *t3_p;
    cudaGetSymbolAddress((void**)&t_p,   g_t);
    cudaGetSymbolAddress((void**)&qkv_p, g_qkv);
    cudaGetSymbolAddress((void**)&o_p,   g_o);
    cudaGetSymbolAddress((void**)&t2_p,  g_t2);
    cudaGetSymbolAddress((void**)&h_p,   g_h);
    cudaGetSymbolAddress((void**)&t3_p,  g_t3);

    int gemm_smem = GEMM_SMEM_FLOATS * 4;
    cudaFuncSetAttribute(gemm_tf32<0>, cudaFuncAttributeMaxDynamicSharedMemorySize, gemm_smem);
    cudaFuncSetAttribute(gemm_tf32<1>, cudaFuncAttributeMaxDynamicSharedMemorySize, gemm_smem);
    cudaFuncSetAttribute(gemm_tf32<2>, cudaFuncAttributeMaxDynamicSharedMemorySize, gemm_smem);
    cudaFuncSetAttribute(gemm_tf32<3>, cudaFuncAttributeMaxDynamicSharedMemorySize, gemm_smem);

    dim3 tb(32, 8);
    dim3 tg(7, 8, BB);

    // 1) x -> t
    transpose_in<<<tg, tb>>>(x, t_p);

    // 2) qkv GEMM (scatter epilogue)
    {
        EpiParams p{};
        p.bias = b_qkv; p.out = qkv_p;
        gemm_tf32<0><<<dim3(768/128, MROWS/128), 256, gemm_smem>>>(t_p, W_qkv, MROWS, 768, CC, p);
    }

    // 3) attention
    {
        int smem_bytes = ATTN_SMEM_FLOATS * 4;
        cudaFuncSetAttribute(attn_kernel, cudaFuncAttributeMaxDynamicSharedMemorySize, smem_bytes);
        attn_kernel<<<BB*NH, 256, smem_bytes>>>(qkv_p, o_p);
    }

    // 4) proj + residual + repbn1
    {
        EpiParams p{};
        p.bias = b_proj; p.resid = t_p;
        p.gamma = gamma1; p.beta = beta1; p.rm = rm1; p.rv = rv1; p.alpha = alpha1;
        p.out = t2_p;
        gemm_tf32<1><<<dim3(CC/128, MROWS/128), 256, gemm_smem>>>(o_p, W_proj, MROWS, CC, CC, p);
    }

    // 5) FFN up + SpatialSILU
    {
        EpiParams p{};
        p.bias = b1; p.saw = sa_w; p.sab = sa_b; p.out = h_p;
        gemm_tf32<2><<<dim3(CM/128, MROWS/128), 256, gemm_smem>>>(t2_p, W1, MROWS, CM, CC, p);
    }

    // 6) FFN down + residual + repbn2
    {
        EpiParams p{};
        p.bias = b2; p.resid = t2_p;
        p.gamma = gamma2; p.beta = beta2; p.rm = rm2; p.rv = rv2; p.alpha = alpha2;
        p.out = t3_p;
        gemm_tf32<3><<<dim3(CC/128, MROWS/128), 256, gemm_smem>>>(h_p, W2, MROWS, CC, CM, p);
    }

    // 7) t3 -> out
    transpose_out<<<tg, tb>>>(t3_p, out);
}

// round 9
// speedup vs baseline: 1.0077x; 1.0077x over previous
#include <cuda_runtime.h>
#include <cuda_bf16.h>
#include <mma.h>
#include <math.h>
#include <cstdint>

using namespace nvcuda;

// ---------------- problem constants ----------------
#define BB   256      // batch
#define CC   256      // channels
#define NN   196      // tokens (14*14)
#define NH   8        // heads
#define DD   32       // head dim
#define CM   2048     // ffn hidden
#define MROWS (BB*NN) // 50176
#define EPSBN 1e-5f

// ---------------- scratch (device globals; no allocations allowed) ----------------
__device__ float g_t [(size_t)MROWS*CC];      // tokens [B*N, C]
__device__ float g_qkv[(size_t)3*BB*NH*NN*DD]; // [part, b, h, n, d]
__device__ float g_o [(size_t)MROWS*CC];      // attention out [B*N, C]
__device__ float g_t2[(size_t)MROWS*CC];      // after repbn1
__device__ float g_h [(size_t)MROWS*CM];      // ffn hidden
__device__ float g_t3[(size_t)MROWS*CC];      // before final transpose

// ---------------- cp.async helpers ----------------
__device__ __forceinline__ void cp_async16(void* smem_dst, const void* gsrc)
{
    unsigned int s = (unsigned int)__cvta_generic_to_shared(smem_dst);
    asm volatile("cp.async.cg.shared.global [%0], [%1], 16;\n" :: "r"(s), "l"(gsrc));
}
__device__ __forceinline__ void cp_commit() { asm volatile("cp.async.commit_group;\n"); }
template <int N>
__device__ __forceinline__ void cp_wait() { asm volatile("cp.async.wait_group %0;\n" :: "n"(N)); }

// ---------------- transposes ----------------
__global__ void transpose_in(const float* __restrict__ x, float* __restrict__ t)
{
    __shared__ float tile[32][33];
    int b  = blockIdx.z;
    int n0 = blockIdx.x * 32;
    int c0 = blockIdx.y * 32;
    int tx = threadIdx.x, ty = threadIdx.y;
#pragma unroll
    for (int i = 0; i < 4; i++) {
        int c = c0 + ty + 8*i;
        int n = n0 + tx;
        if (n < NN) tile[ty + 8*i][tx] = x[((size_t)b*CC + c)*NN + n];
    }
    __syncthreads();
#pragma unroll
    for (int i = 0; i < 4; i++) {
        int n = n0 + ty + 8*i;
        int c = c0 + tx;
        if (n < NN) t[((size_t)b*NN + n)*CC + c] = tile[tx][ty + 8*i];
    }
}

__global__ void transpose_out(const float* __restrict__ t, float* __restrict__ x)
{
    __shared__ float tile[32][33];
    int b  = blockIdx.z;
    int n0 = blockIdx.x * 32;
    int c0 = blockIdx.y * 32;
    int tx = threadIdx.x, ty = threadIdx.y;
#pragma unroll
    for (int i = 0; i < 4; i++) {
        int n = n0 + ty + 8*i;
        int c = c0 + tx;
        if (n < NN) tile[ty + 8*i][tx] = t[((size_t)b*NN + n)*CC + c];
    }
    __syncthreads();
#pragma unroll
    for (int i = 0; i < 4; i++) {
        int c = c0 + ty + 8*i;
        int n = n0 + tx;
        if (n < NN) x[((size_t)b*CC + c)*NN + n] = tile[tx][ty + 8*i];
    }
}

// ---------------- epilogue params ----------------
struct EpiParams {
    const float* bias;
    const float* resid;
    const float* gamma;
    const float* beta;
    const float* rm;
    const float* rv;
    const float* alpha;  // scalar
    const float* saw;    // [B]
    const float* sab;    // [B]
    float*       out;
};

// EPI 0: qkv scatter  | EPI 1: proj + repbn1 | EPI 2: b1 + SpatialSILU | EPI 3: b2 + repbn2
template <int EPI>
__device__ __forceinline__ void apply_epi(int r, int c, float val, const EpiParams& p)
{
    if constexpr (EPI == 0) {
        val += p.bias[c];
        int part = c >> 8;
        int cc   = c & 255;
        int head = cc >> 5;
        int d    = cc & 31;
        int b    = r / NN;
        int n    = r - b * NN;
        size_t PS = (size_t)BB*NH*NN*DD;
        p.out[(size_t)part*PS + (((size_t)(b*NH + head))*NN + n)*DD + d] = val;
    } else if constexpr (EPI == 1 || EPI == 3) {
        val += p.bias[c];
        float tv = p.resid[(size_t)r*CC + c];
        float s  = p.gamma[c] * rsqrtf(p.rv[c] + EPSBN);
        float a  = p.alpha[0];
        float u  = tv + val;
        p.out[(size_t)r*CC + c] = u * (s + a) + (p.beta[c] - p.rm[c]*s);
    } else { // EPI == 2
        val += p.bias[c];
        int b = r / NN;
        float w  = p.saw[b];
        float sb = p.sab[b];
        float wg = w * val + sb;
        float sg = 1.0f / (1.0f + __expf(-wg * val));
        p.out[(size_t)r*CM + c] = val * sg;
    }
}

// ---------------- TF32 tiled GEMM, cp.async 2-stage, 64x64 warp tiles ----------------
// block tile 128x128, K-step 32, 4 warps (4x4 wmma tiles of 16x16 per warp)
// dynamic smem: As[2][128][36] | Bs[2][32][132] | stage[4][256]
// frag loads per kk-step: 8 for 16 MMAs (0.5/MMA) vs 0.75 at 32x64 tiles.
#define AS_STRIDE 36
#define BS_STRIDE 132
#define AS_FLOATS (128*AS_STRIDE)
#define BS_FLOATS (32*BS_STRIDE)
#define GEMM_SMEM_FLOATS (2*AS_FLOATS + 2*BS_FLOATS + 4*256)

template <int EPI>
__global__ __launch_bounds__(128, 2)
void gemm_tf32(const float* __restrict__ A, const float* __restrict__ Bm,
               int M, int N, int K, EpiParams p)
{
    extern __shared__ float sm[];
    float* As  = sm;                       // [2][128][36]
    float* Bs  = sm + 2*AS_FLOATS;         // [2][32][132]
    float* stg = sm + 2*AS_FLOATS + 2*BS_FLOATS; // [4][256]

    int tid  = threadIdx.x;
    int warp = tid >> 5;
    int lane = tid & 31;
    int wm   = warp >> 1;   // 0..1
    int wn   = warp & 1;    // 0..1
    int bn   = blockIdx.x;
    int bm   = blockIdx.y;
    size_t arow0 = (size_t)bm * 128;

    wmma::fragment<wmma::accumulator, 16, 16, 8, float> acc[4][4];
#pragma unroll
    for (int i = 0; i < 4; i++)
#pragma unroll
        for (int j = 0; j < 4; j++)
            wmma::fill_fragment(acc[i][j], 0.0f);

    const float* Abase = A + arow0 * (size_t)K;
    const float* Bbase = Bm + (size_t)bn * 128;

    // async tile loader (128 threads: 8 chunks each for A, 8 for B)
    auto load_tile = [&](int stage, int k0) {
        float* Ad = As + stage * AS_FLOATS;
        float* Bd = Bs + stage * BS_FLOATS;
#pragma unroll
        for (int i = 0; i < 8; i++) {
            int id  = tid + i * 128;       // 0..1023
            int row = id >> 3;             // 0..127
            int c4  = (id & 7) * 4;        // 0..28
            cp_async16(&Ad[row*AS_STRIDE + c4], &Abase[(size_t)row*K + k0 + c4]);
        }
#pragma unroll
        for (int i = 0; i < 8; i++) {
            int id  = tid + i * 128;       // 0..1023
            int row = id >> 5;             // 0..31
            int c4  = (id & 31) * 4;       // 0..124
            cp_async16(&Bd[row*BS_STRIDE + c4], &Bbase[(size_t)(k0 + row)*N + c4]);
        }
        cp_commit();
    };

    int ntiles = K >> 5;
    load_tile(0, 0);

    for (int t = 0; t < ntiles; t++) {
        int cur = t & 1;
        if (t + 1 < ntiles) {
            load_tile((t + 1) & 1, (t + 1) << 5);
            cp_wait<1>();
        } else {
            cp_wait<0>();
        }
        __syncthreads();

        float* Ac = As + cur * AS_FLOATS;
        float* Bc = Bs + cur * BS_FLOATS;
#pragma unroll
        for (int kk = 0; kk < 32; kk += 8) {
            wmma::fragment<wmma::matrix_a, 16, 16, 8, wmma::precision::tf32, wmma::row_major> af[4];
            wmma::fragment<wmma::matrix_b, 16, 16, 8, wmma::precision::tf32, wmma::row_major> bf[4];
#pragma unroll
            for (int i = 0; i < 4; i++)
                wmma::load_matrix_sync(af[i], &Ac[(wm*64 + i*16)*AS_STRIDE + kk], AS_STRIDE);
#pragma unroll
            for (int j = 0; j < 4; j++)
                wmma::load_matrix_sync(bf[j], &Bc[kk*BS_STRIDE + wn*64 + j*16], BS_STRIDE);
#pragma unroll
            for (int i = 0; i < 4; i++)
#pragma unroll
                for (int j = 0; j < 4; j++)
                    wmma::mma_sync(acc[i][j], af[i], bf[j], acc[i][j]);
        }
        __syncthreads();
    }

    // epilogue via per-warp staging
    float* stw = stg + warp * 256;
#pragma unroll
    for (int i = 0; i < 4; i++) {
#pragma unroll
        for (int j = 0; j < 4; j++) {
            wmma::store_matrix_sync(stw, acc[i][j], 16, wmma::mem_row_major);
            __syncwarp();
            int r0 = bm*128 + wm*64 + i*16;
            int c0 = bn*128 + wn*64 + j*16;
#pragma unroll
            for (int q = 0; q < 8; q++) {
                int e  = lane*8 + q;
                int rr = e >> 4;
                int cc = e & 15;
                apply_epi<EPI>(r0 + rr, c0 + cc, stw[e], p);
            }
            __syncwarp();
        }
    }
}

// ---------------- attention: one block per (b, head) ----------------
#define ATTN_SMEM_FLOATS (32*196 + 196*32 + 8*4*32 + 8*196*4)

__global__ __launch_bounds__(256)
void attn_kernel(const float* __restrict__ qkv, float* __restrict__ o)
{
    extern __shared__ float sm[];
    float* kst = sm;                    // [d][j]  d*196 + j
    float* vs  = sm + 32*196;           // [j][d]  j*32 + d
    float* qs  = sm + 2*32*196;         // [w][4][32]
    float* ps  = qs + 8*4*32;           // [w][196][4]

    int bh = blockIdx.x;
    int b  = bh >> 3;
    int h  = bh & 7;
    int tid  = threadIdx.x;
    int w    = tid >> 5;
    int lane = tid & 31;

    size_t PS = (size_t)BB*NH*NN*DD;
    const float* qp = qkv + ((size_t)(b*NH + h))*NN*DD;
    const float* kp = qp + PS;
    const float* vp = qp + 2*PS;

    for (int idx = tid; idx < NN*DD; idx += 256) {
        int j = idx >> 5;
        int d = idx & 31;
        float kv = kp[idx];
        kst[d*NN + j] = kv;
        vs[idx] = vp[idx];
    }
    __syncthreads();

    const float scale = 0.1767766952966369f; // 32^-0.5
    float* qsw = qs + w*128;
    float* psw = ps + w*784;

    int jidx[7]; bool jok[7];
#pragma unroll
    for (int jj = 0; jj < 7; jj++) { jidx[jj] = lane + 32*jj; jok[jj] = jidx[jj] < NN; }

    for (int g = w; g < 49; g += 8) {
        int r0 = g * 4;
#pragma unroll
        for (int t = 0; t < 4; t++)
            qsw[t*32 + lane] = qp[(size_t)(r0 + t)*DD + lane];
        __syncwarp();

        float s[7][4];
#pragma unroll
        for (int jj = 0; jj < 7; jj++)
#pragma unroll
            for (int r = 0; r < 4; r++) s[jj][r] = 0.0f;

        for (int d = 0; d < 32; d++) {
            float qv0 = qsw[0*32 + d];
            float qv1 = qsw[1*32 + d];
            float qv2 = qsw[2*32 + d];
            float qv3 = qsw[3*32 + d];
            const float* krow = &kst[d*NN];
#pragma unroll
            for (int jj = 0; jj < 7; jj++) {
                float kv = jok[jj] ? krow[jidx[jj]] : 0.0f;
                s[jj][0] += qv0 * kv;
                s[jj][1] += qv1 * kv;
                s[jj][2] += qv2 * kv;
                s[jj][3] += qv3 * kv;
            }
        }

#pragma unroll
        for (int r = 0; r < 4; r++) {
            float mx = -INFINITY;
#pragma unroll
            for (int jj = 0; jj < 7; jj++) {
                float sv = jok[jj] ? s[jj][r] * scale : -INFINITY;
                s[jj][r] = sv;
                mx = fmaxf(mx, sv);
            }
#pragma unroll
            for (int off = 16; off > 0; off >>= 1)
                mx = fmaxf(mx, __shfl_xor_sync(0xFFFFFFFFu, mx, off));
            float sum = 0.0f;
#pragma unroll
            for (int jj = 0; jj < 7; jj++) {
                float e = jok[jj] ? __expf(s[jj][r] - mx) : 0.0f;
                s[jj][r] = e;
                sum += e;
            }
#pragma unroll
            for (int off = 16; off > 0; off >>= 1)
                sum += __shfl_xor_sync(0xFFFFFFFFu, sum, off);
            float inv = 1.0f / sum;
#pragma unroll
            for (int jj = 0; jj < 7; jj++)
                if (jok[jj]) psw[jidx[jj]*4 + r] = s[jj][r] * inv;
        }
        __syncwarp();

        float a0 = 0.f, a1 = 0.f, a2 = 0.f, a3 = 0.f;
#pragma unroll 4
        for (int j = 0; j < NN; j++) {
            float4 pv = *(const float4*)&psw[j*4];
            float vv = vs[j*32 + lane];
            a0 += pv.x * vv;
            a1 += pv.y * vv;
            a2 += pv.z * vv;
            a3 += pv.w * vv;
        }
        size_t ob = ((size_t)b*NN + r0)*CC + h*DD + lane;
        o[ob + 0*CC] = a0;
        o[ob + 1*CC] = a1;
        o[ob + 2*CC] = a2;
        o[ob + 3*CC] = a3;
        __syncwarp();
    }
}

// ---------------- launch ----------------
extern "C" void kernel_launch(void* const* d_in, const int* in_sizes, int n_in,
                              void* d_out, int out_size)
{
    const float* x      = (const float*)d_in[0];
    const float* W_qkv  = (const float*)d_in[1];
    const float* b_qkv  = (const float*)d_in[2];
    const float* W_proj = (const float*)d_in[3];
    const float* b_proj = (const float*)d_in[4];
    const float* W1     = (const float*)d_in[5];
    const float* b1     = (const float*)d_in[6];
    const float* W2     = (const float*)d_in[7];
    const float* b2     = (const float*)d_in[8];
    const float* sa_w   = (const float*)d_in[9];
    const float* sa_b   = (const float*)d_in[10];
    const float* alpha1 = (const float*)d_in[11];
    const float* gamma1 = (const float*)d_in[12];
    const float* beta1  = (const float*)d_in[13];
    const float* rm1    = (const float*)d_in[14];
    const float* rv1    = (const float*)d_in[15];
    const float* alpha2 = (const float*)d_in[16];
    const float* gamma2 = (const float*)d_in[17];
    const float* beta2  = (const float*)d_in[18];
    const float* rm2    = (const float*)d_in[19];
    const float* rv2    = (const float*)d_in[20];
    float* out = (float*)d_out;

    float *t_p, *qkv_p, *o_p, *t2_p, *h_p, *t3_p;
    cudaGetSymbolAddress((void**)&t_p,   g_t);
    cudaGetSymbolAddress((void**)&qkv_p, g_qkv);
    cudaGetSymbolAddress((void**)&o_p,   g_o);
    cudaGetSymbolAddress((void**)&t2_p,  g_t2);
    cudaGetSymbolAddress((void**)&h_p,   g_h);
    cudaGetSymbolAddress((void**)&t3_p,  g_t3);

    int gemm_smem = GEMM_SMEM_FLOATS * 4;
    cudaFuncSetAttribute(gemm_tf32<0>, cudaFuncAttributeMaxDynamicSharedMemorySize, gemm_smem);
    cudaFuncSetAttribute(gemm_tf32<1>, cudaFuncAttributeMaxDynamicSharedMemorySize, gemm_smem);
    cudaFuncSetAttribute(gemm_tf32<2>, cudaFuncAttributeMaxDynamicSharedMemorySize, gemm_smem);
    cudaFuncSetAttribute(gemm_tf32<3>, cudaFuncAttributeMaxDynamicSharedMemorySize, gemm_smem);

    dim3 tb(32, 8);
    dim3 tg(7, 8, BB);

    // 1) x -> t
    transpose_in<<<tg, tb>>>(x, t_p);

    // 2) qkv GEMM (scatter epilogue)
    {
        EpiParams p{};
        p.bias = b_qkv; p.out = qkv_p;
        gemm_tf32<0><<<dim3(768/128, MROWS/128), 128, gemm_smem>>>(t_p, W_qkv, MROWS, 768, CC, p);
    }

    // 3) attention
    {
        int smem_bytes = ATTN_SMEM_FLOATS * 4;
        cudaFuncSetAttribute(attn_kernel, cudaFuncAttributeMaxDynamicSharedMemorySize, smem_bytes);
        attn_kernel<<<BB*NH, 256, smem_bytes>>>(qkv_p, o_p);
    }

    // 4) proj + residual + repbn1
    {
        EpiParams p{};
        p.bias = b_proj; p.resid = t_p;
        p.gamma = gamma1; p.beta = beta1; p.rm = rm1; p.rv = rv1; p.alpha = alpha1;
        p.out = t2_p;
        gemm_tf32<1><<<dim3(CC/128, MROWS/128), 128, gemm_smem>>>(o_p, W_proj, MROWS, CC, CC, p);
    }

    // 5) FFN up + SpatialSILU
    {
        EpiParams p{};
        p.bias = b1; p.saw = sa_w; p.sab = sa_b; p.out = h_p;
        gemm_tf32<2><<<dim3(CM/128, MROWS/128), 128, gemm_smem>>>(t2_p, W1, MROWS, CM, CC, p);
    }

    // 6) FFN down + residual + repbn2
    {
        EpiParams p{};
        p.bias = b2; p.resid = t2_p;
        p.gamma = gamma2; p.beta = beta2; p.rm = rm2; p.rv = rv2; p.alpha = alpha2;
        p.out = t3_p;
        gemm_tf32<3><<<dim3(CC/128, MROWS/128), 128, gemm_smem>>>(h_p, W2, MROWS, CC, CM, p);
    }

    // 7) t3 -> out
    transpose_out<<<tg, tb>>>(t3_p, out);
}

// round 10
// speedup vs baseline: 1.5949x; 1.5828x over previous
#include <cuda_runtime.h>
#include <cuda_fp16.h>
#include <mma.h>
#include <math.h>
#include <cstdint>

using namespace nvcuda;

// ---------------- problem constants ----------------
#define BB   256      // batch
#define CC   256      // channels
#define NN   196      // tokens (14*14)
#define NH   8        // heads
#define DD   32       // head dim
#define CM   2048     // ffn hidden
#define MROWS (BB*NN) // 50176
#define EPSBN 1e-5f

// ---------------- scratch (device globals; no allocations allowed) ----------------
__device__ float  g_t  [(size_t)MROWS*CC];       // tokens [B*N, C] f32 (resid for EPI1)
__device__ __half g_th [(size_t)MROWS*CC];       // tokens fp16 (qkv GEMM input)
__device__ float  g_qkv[(size_t)3*BB*NH*NN*DD];  // [part, b, h, n, d] f32
__device__ __half g_oh [(size_t)MROWS*CC];       // attention out fp16 (proj input)
__device__ float  g_t2 [(size_t)MROWS*CC];       // after repbn1 f32 (resid for EPI3)
__device__ __half g_t2h[(size_t)MROWS*CC];       // after repbn1 fp16 (ffn1 input)
__device__ __half g_hh [(size_t)MROWS*CM];       // ffn hidden fp16 (ffn2 input)
__device__ float  g_t3 [(size_t)MROWS*CC];       // before final transpose
__device__ __half g_wh [(size_t)(768*256 + 256*256 + 256*2048 + 2048*256)]; // fp16 weights

#define WQKV_H_OFF  0
#define WPROJ_H_OFF (768*256)
#define W1_H_OFF    (WPROJ_H_OFF + 256*256)
#define W2_H_OFF    (W1_H_OFF + 256*2048)

// ---------------- cp.async helpers ----------------
__device__ __forceinline__ void cp_async16(void* smem_dst, const void* gsrc)
{
    unsigned int s = (unsigned int)__cvta_generic_to_shared(smem_dst);
    asm volatile("cp.async.cg.shared.global [%0], [%1], 16;\n" :: "r"(s), "l"(gsrc));
}
__device__ __forceinline__ void cp_commit() { asm volatile("cp.async.commit_group;\n"); }
template <int N>
__device__ __forceinline__ void cp_wait() { asm volatile("cp.async.wait_group %0;\n" :: "n"(N)); }

// ---------------- conversion kernel: f32 -> fp16 (rn), 4 elems/thread ----------------
__global__ void f2h_kernel(const float* __restrict__ in, __half* __restrict__ out, int n4)
{
    int i = blockIdx.x * 256 + threadIdx.x;
    if (i < n4) {
        float4 v = ((const float4*)in)[i];
        __half2* o2 = (__half2*)out;
        o2[i*2 + 0] = __floats2half2_rn(v.x, v.y);
        o2[i*2 + 1] = __floats2half2_rn(v.z, v.w);
    }
}

// ---------------- transposes ----------------
__global__ void transpose_in(const float* __restrict__ x, float* __restrict__ t,
                             __half* __restrict__ th)
{
    __shared__ float tile[32][33];
    int b  = blockIdx.z;
    int n0 = blockIdx.x * 32;
    int c0 = blockIdx.y * 32;
    int tx = threadIdx.x, ty = threadIdx.y;
#pragma unroll
    for (int i = 0; i < 4; i++) {
        int c = c0 + ty + 8*i;
        int n = n0 + tx;
        if (n < NN) tile[ty + 8*i][tx] = x[((size_t)b*CC + c)*NN + n];
    }
    __syncthreads();
#pragma unroll
    for (int i = 0; i < 4; i++) {
        int n = n0 + ty + 8*i;
        int c = c0 + tx;
        if (n < NN) {
            float v = tile[tx][ty + 8*i];
            size_t idx = ((size_t)b*NN + n)*CC + c;
            t[idx]  = v;
            th[idx] = __float2half_rn(v);
        }
    }
}

__global__ void transpose_out(const float* __restrict__ t, float* __restrict__ x)
{
    __shared__ float tile[32][33];
    int b  = blockIdx.z;
    int n0 = blockIdx.x * 32;
    int c0 = blockIdx.y * 32;
    int tx = threadIdx.x, ty = threadIdx.y;
#pragma unroll
    for (int i = 0; i < 4; i++) {
        int n = n0 + ty + 8*i;
        int c = c0 + tx;
        if (n < NN) tile[ty + 8*i][tx] = t[((size_t)b*NN + n)*CC + c];
    }
    __syncthreads();
#pragma unroll
    for (int i = 0; i < 4; i++) {
        int c = c0 + ty + 8*i;
        int n = n0 + tx;
        if (n < NN) x[((size_t)b*CC + c)*NN + n] = tile[tx][ty + 8*i];
    }
}

// ---------------- epilogue params ----------------
struct EpiParams {
    const float* bias;
    const float* resid;
    const float* gamma;
    const float* beta;
    const float* rm;
    const float* rv;
    const float* alpha;  // scalar
    const float* saw;    // [B]
    const float* sab;    // [B]
    float*       out;
    __half*      outh;
};

// EPI 0: qkv scatter (f32) | EPI 1: proj+repbn1 (f32 + fp16) | EPI 2: b1+SpatialSILU (fp16) | EPI 3: b2+repbn2 (f32)
template <int EPI>
__device__ __forceinline__ void apply_epi(int r, int c, float val, const EpiParams& p)
{
    if constexpr (EPI == 0) {
        val += p.bias[c];
        int part = c >> 8;
        int cc   = c & 255;
        int head = cc >> 5;
        int d    = cc & 31;
        int b    = r / NN;
        int n    = r - b * NN;
        size_t PS = (size_t)BB*NH*NN*DD;
        p.out[(size_t)part*PS + (((size_t)(b*NH + head))*NN + n)*DD + d] = val;
    } else if constexpr (EPI == 1) {
        val += p.bias[c];
        float tv = p.resid[(size_t)r*CC + c];
        float s  = p.gamma[c] * rsqrtf(p.rv[c] + EPSBN);
        float a  = p.alpha[0];
        float u  = tv + val;
        float res = u * (s + a) + (p.beta[c] - p.rm[c]*s);
        p.out [(size_t)r*CC + c] = res;
        p.outh[(size_t)r*CC + c] = __float2half_rn(res);
    } else if constexpr (EPI == 3) {
        val += p.bias[c];
        float tv = p.resid[(size_t)r*CC + c];
        float s  = p.gamma[c] * rsqrtf(p.rv[c] + EPSBN);
        float a  = p.alpha[0];
        float u  = tv + val;
        p.out[(size_t)r*CC + c] = u * (s + a) + (p.beta[c] - p.rm[c]*s);
    } else { // EPI == 2
        val += p.bias[c];
        int b = r / NN;
        float w  = p.saw[b];
        float sb = p.sab[b];
        float wg = w * val + sb;
        float sg = 1.0f / (1.0f + __expf(-wg * val));
        p.outh[(size_t)r*CM + c] = __float2half_rn(val * sg);
    }
}

// ---------------- FP16 tiled GEMM, cp.async 2-stage, 64x64 warp tiles ----------------
// block tile 128x128, K-step 64, 4 warps (4x4 wmma m16n16k16 per warp), f32 accum
// dynamic smem (bytes): Ah[2][128][72]h | Bh[2][64][136]h | stage[4][256]f
#define AH_STRIDE 72
#define BH_STRIDE 136
#define AH_BYTES (128*AH_STRIDE*2)   // 18432
#define BH_BYTES (64*BH_STRIDE*2)    // 17408
#define GEMM_SMEM_BYTES (2*AH_BYTES + 2*BH_BYTES + 4*256*4)  // 75776

template <int EPI>
__global__ __launch_bounds__(128, 2)
void gemm_h(const __half* __restrict__ A, const __half* __restrict__ Bm,
            int M, int N, int K, EpiParams p)
{
    extern __shared__ char dynsm[];
    __half* Ah  = (__half*)dynsm;                          // [2][128][72]
    __half* Bh  = (__half*)(dynsm + 2*AH_BYTES);           // [2][64][136]
    float*  stg = (float*)(dynsm + 2*AH_BYTES + 2*BH_BYTES); // [4][256]

    int tid  = threadIdx.x;
    int warp = tid >> 5;
    int lane = tid & 31;
    int wm   = warp >> 1;   // 0..1
    int wn   = warp & 1;    // 0..1
    int bn   = blockIdx.x;
    int bm   = blockIdx.y;
    size_t arow0 = (size_t)bm * 128;

    wmma::fragment<wmma::accumulator, 16, 16, 16, float> acc[4][4];
#pragma unroll
    for (int i = 0; i < 4; i++)
#pragma unroll
        for (int j = 0; j < 4; j++)
            wmma::fill_fragment(acc[i][j], 0.0f);

    const __half* Abase = A + arow0 * (size_t)K;
    const __half* Bbase = Bm + (size_t)bn * 128;

    // async tile loader: A = 128 rows x 64 halves (8 chunks/row), B = 64 rows x 128 halves (16 chunks/row)
    auto load_tile = [&](int stage, int k0) {
        __half* Ad = Ah + stage * (AH_BYTES/2);
        __half* Bd = Bh + stage * (BH_BYTES/2);
#pragma unroll
        for (int i = 0; i < 8; i++) {
            int id  = tid + i * 128;       // 0..1023
            int row = id >> 3;             // 0..127
            int c8  = (id & 7) * 8;        // 0..56
            cp_async16(&Ad[row*AH_STRIDE + c8], &Abase[(size_t)row*K + k0 + c8]);
        }
#pragma unroll
        for (int i = 0; i < 8; i++) {
            int id  = tid + i * 128;       // 0..1023
            int row = id >> 4;             // 0..63
            int c8  = (id & 15) * 8;       // 0..120
            cp_async16(&Bd[row*BH_STRIDE + c8], &Bbase[(size_t)(k0 + row)*N + c8]);
        }
        cp_commit();
    };

    int ntiles = K >> 6;
    load_tile(0, 0);

    for (int t = 0; t < ntiles; t++) {
        int cur = t & 1;
        if (t + 1 < ntiles) {
            load_tile((t + 1) & 1, (t + 1) << 6);
            cp_wait<1>();
        } else {
            cp_wait<0>();
        }
        __syncthreads();

        __half* Ac = Ah + cur * (AH_BYTES/2);
        __half* Bc = Bh + cur * (BH_BYTES/2);
#pragma unroll
        for (int kk = 0; kk < 64; kk += 16) {
            wmma::fragment<wmma::matrix_a, 16, 16, 16, __half, wmma::row_major> af[4];
            wmma::fragment<wmma::matrix_b, 16, 16, 16, __half, wmma::row_major> bf[4];
#pragma unroll
            for (int i = 0; i < 4; i++)
                wmma::load_matrix_sync(af[i], &Ac[(wm*64 + i*16)*AH_STRIDE + kk], AH_STRIDE);
#pragma unroll
            for (int j = 0; j < 4; j++)
                wmma::load_matrix_sync(bf[j], &Bc[kk*BH_STRIDE + wn*64 + j*16], BH_STRIDE);
#pragma unroll
            for (int i = 0; i < 4; i++)
#pragma unroll
                for (int j = 0; j < 4; j++)
                    wmma::mma_sync(acc[i][j], af[i], bf[j], acc[i][j]);
        }
        __syncthreads();
    }

    // epilogue via per-warp staging
    float* stw = stg + warp * 256;
#pragma unroll
    for (int i = 0; i < 4; i++) {
#pragma unroll
        for (int j = 0; j < 4; j++) {
            wmma::store_matrix_sync(stw, acc[i][j], 16, wmma::mem_row_major);
            __syncwarp();
            int r0 = bm*128 + wm*64 + i*16;
            int c0 = bn*128 + wn*64 + j*16;
#pragma unroll
            for (int q = 0; q < 8; q++) {
                int e  = lane*8 + q;
                int rr = e >> 4;
                int cc = e & 15;
                apply_epi<EPI>(r0 + rr, c0 + cc, stw[e], p);
            }
            __syncwarp();
        }
    }
}

// ---------------- attention: one block per (b, head) ----------------
#define ATTN_SMEM_FLOATS (32*196 + 196*32 + 8*4*32 + 8*196*4)

__global__ __launch_bounds__(256)
void attn_kernel(const float* __restrict__ qkv, __half* __restrict__ o)
{
    extern __shared__ float sm[];
    float* kst = sm;                    // [d][j]  d*196 + j
    float* vs  = sm + 32*196;           // [j][d]  j*32 + d
    float* qs  = sm + 2*32*196;         // [w][4][32]
    float* ps  = qs + 8*4*32;           // [w][196][4]

    int bh = blockIdx.x;
    int b  = bh >> 3;
    int h  = bh & 7;
    int tid  = threadIdx.x;
    int w    = tid >> 5;
    int lane = tid & 31;

    size_t PS = (size_t)BB*NH*NN*DD;
    const float* qp = qkv + ((size_t)(b*NH + h))*NN*DD;
    const float* kp = qp + PS;
    const float* vp = qp + 2*PS;

    for (int idx = tid; idx < NN*DD; idx += 256) {
        int j = idx >> 5;
        int d = idx & 31;
        float kv = kp[idx];
        kst[d*NN + j] = kv;
        vs[idx] = vp[idx];
    }
    __syncthreads();

    const float scale = 0.1767766952966369f; // 32^-0.5
    float* qsw = qs + w*128;
    float* psw = ps + w*784;

    int jidx[7]; bool jok[7];
#pragma unroll
    for (int jj = 0; jj < 7; jj++) { jidx[jj] = lane + 32*jj; jok[jj] = jidx[jj] < NN; }

    for (int g = w; g < 49; g += 8) {
        int r0 = g * 4;
#pragma unroll
        for (int t = 0; t < 4; t++)
            qsw[t*32 + lane] = qp[(size_t)(r0 + t)*DD + lane];
        __syncwarp();

        float s[7][4];
#pragma unroll
        for (int jj = 0; jj < 7; jj++)
#pragma unroll
            for (int r = 0; r < 4; r++) s[jj][r] = 0.0f;

        for (int d = 0; d < 32; d++) {
            float qv0 = qsw[0*32 + d];
            float qv1 = qsw[1*32 + d];
            float qv2 = qsw[2*32 + d];
            float qv3 = qsw[3*32 + d];
            const float* krow = &kst[d*NN];
#pragma unroll
            for (int jj = 0; jj < 7; jj++) {
                float kv = jok[jj] ? krow[jidx[jj]] : 0.0f;
                s[jj][0] += qv0 * kv;
                s[jj][1] += qv1 * kv;
                s[jj][2] += qv2 * kv;
                s[jj][3] += qv3 * kv;
            }
        }

#pragma unroll
        for (int r = 0; r < 4; r++) {
            float mx = -INFINITY;
#pragma unroll
            for (int jj = 0; jj < 7; jj++) {
                float sv = jok[jj] ? s[jj][r] * scale : -INFINITY;
                s[jj][r] = sv;
                mx = fmaxf(mx, sv);
            }
#pragma unroll
            for (int off = 16; off > 0; off >>= 1)
                mx = fmaxf(mx, __shfl_xor_sync(0xFFFFFFFFu, mx, off));
            float sum = 0.0f;
#pragma unroll
            for (int jj = 0; jj < 7; jj++) {
                float e = jok[jj] ? __expf(s[jj][r] - mx) : 0.0f;
                s[jj][r] = e;
                sum += e;
            }
#pragma unroll
            for (int off = 16; off > 0; off >>= 1)
                sum += __shfl_xor_sync(0xFFFFFFFFu, sum, off);
            float inv = 1.0f / sum;
#pragma unroll
            for (int jj = 0; jj < 7; jj++)
                if (jok[jj]) psw[jidx[jj]*4 + r] = s[jj][r] * inv;
        }
        __syncwarp();

        float a0 = 0.f, a1 = 0.f, a2 = 0.f, a3 = 0.f;
#pragma unroll 4
        for (int j = 0; j < NN; j++) {
            float4 pv = *(const float4*)&psw[j*4];
            float vv = vs[j*32 + lane];
            a0 += pv.x * vv;
            a1 += pv.y * vv;
            a2 += pv.z * vv;
            a3 += pv.w * vv;
        }
        size_t ob = ((size_t)b*NN + r0)*CC + h*DD + lane;
        o[ob + 0*CC] = __float2half_rn(a0);
        o[ob + 1*CC] = __float2half_rn(a1);
        o[ob + 2*CC] = __float2half_rn(a2);
        o[ob + 3*CC] = __float2half_rn(a3);
        __syncwarp();
    }
}

// ---------------- launch ----------------
extern "C" void kernel_launch(void* const* d_in, const int* in_sizes, int n_in,
                              void* d_out, int out_size)
{
    const float* x      = (const float*)d_in[0];
    const float* W_qkv  = (const float*)d_in[1];
    const float* b_qkv  = (const float*)d_in[2];
    const float* W_proj = (const float*)d_in[3];
    const float* b_proj = (const float*)d_in[4];
    const float* W1     = (const float*)d_in[5];
    const float* b1     = (const float*)d_in[6];
    const float* W2     = (const float*)d_in[7];
    const float* b2     = (const float*)d_in[8];
    const float* sa_w   = (const float*)d_in[9];
    const float* sa_b   = (const float*)d_in[10];
    const float* alpha1 = (const float*)d_in[11];
    const float* gamma1 = (const float*)d_in[12];
    const float* beta1  = (const float*)d_in[13];
    const float* rm1    = (const float*)d_in[14];
    const float* rv1    = (const float*)d_in[15];
    const float* alpha2 = (const float*)d_in[16];
    const float* gamma2 = (const float*)d_in[17];
    const float* beta2  = (const float*)d_in[18];
    const float* rm2    = (const float*)d_in[19];
    const float* rv2    = (const float*)d_in[20];
    float* out = (float*)d_out;

    float *t_p, *qkv_p, *t2_p, *t3_p;
    __half *th_p, *oh_p, *t2h_p, *hh_p, *wh_p;
    cudaGetSymbolAddress((void**)&t_p,   g_t);
    cudaGetSymbolAddress((void**)&th_p,  g_th);
    cudaGetSymbolAddress((void**)&qkv_p, g_qkv);
    cudaGetSymbolAddress((void**)&oh_p,  g_oh);
    cudaGetSymbolAddress((void**)&t2_p,  g_t2);
    cudaGetSymbolAddress((void**)&t2h_p, g_t2h);
    cudaGetSymbolAddress((void**)&hh_p,  g_hh);
    cudaGetSymbolAddress((void**)&t3_p,  g_t3);
    cudaGetSymbolAddress((void**)&wh_p,  g_wh);

    cudaFuncSetAttribute(gemm_h<0>, cudaFuncAttributeMaxDynamicSharedMemorySize, GEMM_SMEM_BYTES);
    cudaFuncSetAttribute(gemm_h<1>, cudaFuncAttributeMaxDynamicSharedMemorySize, GEMM_SMEM_BYTES);
    cudaFuncSetAttribute(gemm_h<2>, cudaFuncAttributeMaxDynamicSharedMemorySize, GEMM_SMEM_BYTES);
    cudaFuncSetAttribute(gemm_h<3>, cudaFuncAttributeMaxDynamicSharedMemorySize, GEMM_SMEM_BYTES);

    dim3 tb(32, 8);
    dim3 tg(7, 8, BB);

    // 0) weight conversions f32 -> fp16
    f2h_kernel<<<(768*256/4 + 255)/256, 256>>>(W_qkv,  wh_p + WQKV_H_OFF,  768*256/4);
    f2h_kernel<<<(256*256/4 + 255)/256, 256>>>(W_proj, wh_p + WPROJ_H_OFF, 256*256/4);
    f2h_kernel<<<(256*2048/4 + 255)/256, 256>>>(W1,    wh_p + W1_H_OFF,    256*2048/4);
    f2h_kernel<<<(2048*256/4 + 255)/256, 256>>>(W2,    wh_p + W2_H_OFF,    2048*256/4);

    // 1) x -> t (f32 + fp16)
    transpose_in<<<tg, tb>>>(x, t_p, th_p);

    // 2) qkv GEMM (scatter epilogue, f32 out)
    {
        EpiParams p{};
        p.bias = b_qkv; p.out = qkv_p;
        gemm_h<0><<<dim3(768/128, MROWS/128), 128, GEMM_SMEM_BYTES>>>(th_p, wh_p + WQKV_H_OFF, MROWS, 768, CC, p);
    }

    // 3) attention (f32 internal, fp16 out)
    {
        int smem_bytes = ATTN_SMEM_FLOATS * 4;
        cudaFuncSetAttribute(attn_kernel, cudaFuncAttributeMaxDynamicSharedMemorySize, smem_bytes);
        attn_kernel<<<BB*NH, 256, smem_bytes>>>(qkv_p, oh_p);
    }

    // 4) proj + residual + repbn1 (f32 + fp16 out)
    {
        EpiParams p{};
        p.bias = b_proj; p.resid = t_p;
        p.gamma = gamma1; p.beta = beta1; p.rm = rm1; p.rv = rv1; p.alpha = alpha1;
        p.out = t2_p; p.outh = t2h_p;
        gemm_h<1><<<dim3(CC/128, MROWS/128), 128, GEMM_SMEM_BYTES>>>(oh_p, wh_p + WPROJ_H_OFF, MROWS, CC, CC, p);
    }

    // 5) FFN up + SpatialSILU (fp16 out)
    {
        EpiParams p{};
        p.bias = b1; p.saw = sa_w; p.sab = sa_b; p.outh = hh_p;
        gemm_h<2><<<dim3(CM/128, MROWS/128), 128, GEMM_SMEM_BYTES>>>(t2h_p, wh_p + W1_H_OFF, MROWS, CM, CC, p);
    }

    // 6) FFN down + residual + repbn2 (f32 out)
    {
        EpiParams p{};
        p.bias = b2; p.resid = t2_p;
        p.gamma = gamma2; p.beta = beta2; p.rm = rm2; p.rv = rv2; p.alpha = alpha2;
        p.out = t3_p;
        gemm_h<3><<<dim3(CC/128, MROWS/128), 128, GEMM_SMEM_BYTES>>>(hh_p, wh_p + W2_H_OFF, MROWS, CC, CM, p);
    }

    // 7) t3 -> out
    transpose_out<<<tg, tb>>>(t3_p, out);
}

// round 11
// speedup vs baseline: 1.7197x; 1.0783x over previous
#include <cuda_runtime.h>
#include <cuda_fp16.h>
#include <mma.h>
#include <math.h>
#include <cstdint>

using namespace nvcuda;

// ---------------- problem constants ----------------
#define BB   256      // batch
#define CC   256      // channels
#define NN   196      // tokens (14*14)
#define NH   8        // heads
#define DD   32       // head dim
#define CM   2048     // ffn hidden
#define MROWS (BB*NN) // 50176
#define EPSBN 1e-5f

// ---------------- scratch (device globals; no allocations allowed) ----------------
__device__ float  g_t  [(size_t)MROWS*CC];        // tokens [B*N, C] f32 (resid for EPI1)
__device__ __half g_th [(size_t)MROWS*CC];        // tokens fp16 (qkv GEMM input)
__device__ __half g_qkvh[(size_t)3*BB*NH*NN*DD];  // [part, b, h, n, d] fp16
__device__ __half g_oh [(size_t)MROWS*CC];        // attention out fp16 (proj input)
__device__ float  g_t2 [(size_t)MROWS*CC];        // after repbn1 f32 (resid for EPI3)
__device__ __half g_t2h[(size_t)MROWS*CC];        // after repbn1 fp16 (ffn1 input)
__device__ __half g_hh [(size_t)MROWS*CM];        // ffn hidden fp16 (ffn2 input)
__device__ float  g_t3 [(size_t)MROWS*CC];        // before final transpose
__device__ __half g_wh [(size_t)(768*256 + 256*256 + 256*2048 + 2048*256)]; // fp16 weights

#define WQKV_H_OFF  0
#define WPROJ_H_OFF (768*256)
#define W1_H_OFF    (WPROJ_H_OFF + 256*256)
#define W2_H_OFF    (W1_H_OFF + 256*2048)

// ---------------- cp.async helpers ----------------
__device__ __forceinline__ void cp_async16(void* smem_dst, const void* gsrc)
{
    unsigned int s = (unsigned int)__cvta_generic_to_shared(smem_dst);
    asm volatile("cp.async.cg.shared.global [%0], [%1], 16;\n" :: "r"(s), "l"(gsrc));
}
__device__ __forceinline__ void cp_commit() { asm volatile("cp.async.commit_group;\n"); }
template <int N>
__device__ __forceinline__ void cp_wait() { asm volatile("cp.async.wait_group %0;\n" :: "n"(N)); }

// ---------------- single f32->fp16 conversion over all 4 weight tensors ----------------
// float4 boundaries: qkv 49152 | proj 65536 | w1 196608 | w2 327680
__global__ void f2h_all(const float* __restrict__ w_qkv, const float* __restrict__ w_proj,
                        const float* __restrict__ w1, const float* __restrict__ w2,
                        __half* __restrict__ dst)
{
    int i = blockIdx.x * 256 + threadIdx.x;
    if (i >= 327680) return;
    const float* src; int off;
    if      (i < 49152)  { src = w_qkv;  off = 0; }
    else if (i < 65536)  { src = w_proj; off = 49152; }
    else if (i < 196608) { src = w1;     off = 65536; }
    else                 { src = w2;     off = 196608; }
    float4 v = ((const float4*)src)[i - off];
    __half2* o2 = (__half2*)dst;
    o2[i*2 + 0] = __floats2half2_rn(v.x, v.y);
    o2[i*2 + 1] = __floats2half2_rn(v.z, v.w);
}

// ---------------- transposes ----------------
__global__ void transpose_in(const float* __restrict__ x, float* __restrict__ t,
                             __half* __restrict__ th)
{
    __shared__ float tile[32][33];
    int b  = blockIdx.z;
    int n0 = blockIdx.x * 32;
    int c0 = blockIdx.y * 32;
    int tx = threadIdx.x, ty = threadIdx.y;
#pragma unroll
    for (int i = 0; i < 4; i++) {
        int c = c0 + ty + 8*i;
        int n = n0 + tx;
        if (n < NN) tile[ty + 8*i][tx] = x[((size_t)b*CC + c)*NN + n];
    }
    __syncthreads();
#pragma unroll
    for (int i = 0; i < 4; i++) {
        int n = n0 + ty + 8*i;
        int c = c0 + tx;
        if (n < NN) {
            float v = tile[tx][ty + 8*i];
            size_t idx = ((size_t)b*NN + n)*CC + c;
            t[idx]  = v;
            th[idx] = __float2half_rn(v);
        }
    }
}

__global__ void transpose_out(const float* __restrict__ t, float* __restrict__ x)
{
    __shared__ float tile[32][33];
    int b  = blockIdx.z;
    int n0 = blockIdx.x * 32;
    int c0 = blockIdx.y * 32;
    int tx = threadIdx.x, ty = threadIdx.y;
#pragma unroll
    for (int i = 0; i < 4; i++) {
        int n = n0 + ty + 8*i;
        int c = c0 + tx;
        if (n < NN) tile[ty + 8*i][tx] = t[((size_t)b*NN + n)*CC + c];
    }
    __syncthreads();
#pragma unroll
    for (int i = 0; i < 4; i++) {
        int c = c0 + ty + 8*i;
        int n = n0 + tx;
        if (n < NN) x[((size_t)b*CC + c)*NN + n] = tile[tx][ty + 8*i];
    }
}

// ---------------- epilogue params ----------------
struct EpiParams {
    const float* bias;
    const float* resid;
    const float* gamma;
    const float* beta;
    const float* rm;
    const float* rv;
    const float* alpha;  // scalar
    const float* saw;    // [B]
    const float* sab;    // [B]
    float*       out;
    __half*      outh;
};

// EPI 0: qkv scatter (fp16) | EPI 1: proj+repbn1 (f32+fp16) | EPI 2: b1+SpatialSILU (fp16) | EPI 3: b2+repbn2 (f32)
template <int EPI>
__device__ __forceinline__ void apply_epi(int r, int c, float val, const EpiParams& p)
{
    if constexpr (EPI == 0) {
        val += p.bias[c];
        int part = c >> 8;
        int cc   = c & 255;
        int head = cc >> 5;
        int d    = cc & 31;
        int b    = r / NN;
        int n    = r - b * NN;
        size_t PS = (size_t)BB*NH*NN*DD;
        p.outh[(size_t)part*PS + (((size_t)(b*NH + head))*NN + n)*DD + d] = __float2half_rn(val);
    } else if constexpr (EPI == 1) {
        val += p.bias[c];
        float tv = p.resid[(size_t)r*CC + c];
        float s  = p.gamma[c] * rsqrtf(p.rv[c] + EPSBN);
        float a  = p.alpha[0];
        float u  = tv + val;
        float res = u * (s + a) + (p.beta[c] - p.rm[c]*s);
        p.out [(size_t)r*CC + c] = res;
        p.outh[(size_t)r*CC + c] = __float2half_rn(res);
    } else if constexpr (EPI == 3) {
        val += p.bias[c];
        float tv = p.resid[(size_t)r*CC + c];
        float s  = p.gamma[c] * rsqrtf(p.rv[c] + EPSBN);
        float a  = p.alpha[0];
        float u  = tv + val;
        p.out[(size_t)r*CC + c] = u * (s + a) + (p.beta[c] - p.rm[c]*s);
    } else { // EPI == 2
        val += p.bias[c];
        int b = r / NN;
        float w  = p.saw[b];
        float sb = p.sab[b];
        float wg = w * val + sb;
        float sg = 1.0f / (1.0f + __expf(-wg * val));
        p.outh[(size_t)r*CM + c] = __float2half_rn(val * sg);
    }
}

// ---------------- FP16 tiled GEMM, cp.async 2-stage, 64x64 warp tiles ----------------
#define AH_STRIDE 72
#define BH_STRIDE 136
#define AH_BYTES (128*AH_STRIDE*2)   // 18432
#define BH_BYTES (64*BH_STRIDE*2)    // 17408
#define GEMM_SMEM_BYTES (2*AH_BYTES + 2*BH_BYTES + 4*256*4)  // 75776

template <int EPI>
__global__ __launch_bounds__(128, 2)
void gemm_h(const __half* __restrict__ A, const __half* __restrict__ Bm,
            int M, int N, int K, EpiParams p)
{
    extern __shared__ char dynsm[];
    __half* Ah  = (__half*)dynsm;                          // [2][128][72]
    __half* Bh  = (__half*)(dynsm + 2*AH_BYTES);           // [2][64][136]
    float*  stg = (float*)(dynsm + 2*AH_BYTES + 2*BH_BYTES); // [4][256]

    int tid  = threadIdx.x;
    int warp = tid >> 5;
    int lane = tid & 31;
    int wm   = warp >> 1;
    int wn   = warp & 1;
    int bn   = blockIdx.x;
    int bm   = blockIdx.y;
    size_t arow0 = (size_t)bm * 128;

    wmma::fragment<wmma::accumulator, 16, 16, 16, float> acc[4][4];
#pragma unroll
    for (int i = 0; i < 4; i++)
#pragma unroll
        for (int j = 0; j < 4; j++)
            wmma::fill_fragment(acc[i][j], 0.0f);

    const __half* Abase = A + arow0 * (size_t)K;
    const __half* Bbase = Bm + (size_t)bn * 128;

    auto load_tile = [&](int stage, int k0) {
        __half* Ad = Ah + stage * (AH_BYTES/2);
        __half* Bd = Bh + stage * (BH_BYTES/2);
#pragma unroll
        for (int i = 0; i < 8; i++) {
            int id  = tid + i * 128;
            int row = id >> 3;
            int c8  = (id & 7) * 8;
            cp_async16(&Ad[row*AH_STRIDE + c8], &Abase[(size_t)row*K + k0 + c8]);
        }
#pragma unroll
        for (int i = 0; i < 8; i++) {
            int id  = tid + i * 128;
            int row = id >> 4;
            int c8  = (id & 15) * 8;
            cp_async16(&Bd[row*BH_STRIDE + c8], &Bbase[(size_t)(k0 + row)*N + c8]);
        }
        cp_commit();
    };

    int ntiles = K >> 6;
    load_tile(0, 0);

    for (int t = 0; t < ntiles; t++) {
        int cur = t & 1;
        if (t + 1 < ntiles) {
            load_tile((t + 1) & 1, (t + 1) << 6);
            cp_wait<1>();
        } else {
            cp_wait<0>();
        }
        __syncthreads();

        __half* Ac = Ah + cur * (AH_BYTES/2);
        __half* Bc = Bh + cur * (BH_BYTES/2);
#pragma unroll
        for (int kk = 0; kk < 64; kk += 16) {
            wmma::fragment<wmma::matrix_a, 16, 16, 16, __half, wmma::row_major> af[4];
            wmma::fragment<wmma::matrix_b, 16, 16, 16, __half, wmma::row_major> bf[4];
#pragma unroll
            for (int i = 0; i < 4; i++)
                wmma::load_matrix_sync(af[i], &Ac[(wm*64 + i*16)*AH_STRIDE + kk], AH_STRIDE);
#pragma unroll
            for (int j = 0; j < 4; j++)
                wmma::load_matrix_sync(bf[j], &Bc[kk*BH_STRIDE + wn*64 + j*16], BH_STRIDE);
#pragma unroll
            for (int i = 0; i < 4; i++)
#pragma unroll
                for (int j = 0; j < 4; j++)
                    wmma::mma_sync(acc[i][j], af[i], bf[j], acc[i][j]);
        }
        __syncthreads();
    }

    float* stw = stg + warp * 256;
#pragma unroll
    for (int i = 0; i < 4; i++) {
#pragma unroll
        for (int j = 0; j < 4; j++) {
            wmma::store_matrix_sync(stw, acc[i][j], 16, wmma::mem_row_major);
            __syncwarp();
            int r0 = bm*128 + wm*64 + i*16;
            int c0 = bn*128 + wn*64 + j*16;
#pragma unroll
            for (int q = 0; q < 8; q++) {
                int e  = lane*8 + q;
                int rr = e >> 4;
                int cc = e & 15;
                apply_epi<EPI>(r0 + rr, c0 + cc, stw[e], p);
            }
            __syncwarp();
        }
    }
}

// ---------------- tensor-core attention: one block per (b, head) ----------------
// smem: Qs/Ks/Vs fp16 [208][32] + S f32 [208][216]
#define AT_NP   208
#define AT_SSTR 216
#define AT_QKV_BYTES (AT_NP*32*2)        // 13312
#define AT_SMEM_BYTES (3*AT_QKV_BYTES + AT_NP*AT_SSTR*4)  // 219648

__global__ __launch_bounds__(256)
void attn_tc(const __half* __restrict__ qkv, __half* __restrict__ o)
{
    extern __shared__ char smc[];
    __half* Qs = (__half*)smc;
    __half* Ks = (__half*)(smc + AT_QKV_BYTES);
    __half* Vs = (__half*)(smc + 2*AT_QKV_BYTES);
    float*  S  = (float*)(smc + 3*AT_QKV_BYTES);

    int bh = blockIdx.x;
    int b  = bh >> 3;
    int h  = bh & 7;
    int tid  = threadIdx.x;
    int w    = tid >> 5;
    int lane = tid & 31;

    size_t PS = (size_t)BB*NH*NN*DD;
    const __half* qp = qkv + (size_t)bh*NN*DD;
    const __half* kp = qp + PS;
    const __half* vp = qp + 2*PS;

    // load Q,K,V with zero padding to 208 rows
    const __half hz = __float2half(0.0f);
    for (int idx = tid; idx < AT_NP*DD; idx += 256) {
        int row = idx >> 5;
        __half q = hz, k = hz, v = hz;
        if (row < NN) { q = qp[idx]; k = kp[idx]; v = vp[idx]; }
        Qs[idx] = q; Ks[idx] = k; Vs[idx] = v;
    }
    __syncthreads();

    // S = Q @ K^T   (13x13 tiles of m16n16k16, 2 k-steps)
    for (int t = w; t < 169; t += 8) {
        int mt = t / 13, nt = t - mt*13;
        wmma::fragment<wmma::accumulator, 16, 16, 16, float> c;
        wmma::fill_fragment(c, 0.0f);
#pragma unroll
        for (int k0 = 0; k0 < 32; k0 += 16) {
            wmma::fragment<wmma::matrix_a, 16, 16, 16, __half, wmma::row_major> af;
            wmma::fragment<wmma::matrix_b, 16, 16, 16, __half, wmma::col_major> bf;
            wmma::load_matrix_sync(af, Qs + (mt*16)*32 + k0, 32);
            wmma::load_matrix_sync(bf, Ks + (nt*16)*32 + k0, 32);
            wmma::mma_sync(c, af, bf, c);
        }
        wmma::store_matrix_sync(&S[(size_t)mt*16*AT_SSTR + nt*16], c, AT_SSTR, wmma::mem_row_major);
    }
    __syncthreads();

    // softmax rows (f32), write P as fp16 in place (stride 2*AT_SSTR halves)
    const float scale = 0.1767766952966369f;
    __half* P = (__half*)S;
    for (int r = w; r < AT_NP; r += 8) {
        float* Srow = S + (size_t)r*AT_SSTR;
        float vreg[7];
#pragma unroll
        for (int i = 0; i < 7; i++) {
            int j = lane + 32*i;
            vreg[i] = (j < NN) ? Srow[j]*scale : -INFINITY;
        }
        float mx = -INFINITY;
#pragma unroll
        for (int i = 0; i < 7; i++) mx = fmaxf(mx, vreg[i]);
#pragma unroll
        for (int off = 16; off > 0; off >>= 1)
            mx = fmaxf(mx, __shfl_xor_sync(0xFFFFFFFFu, mx, off));
        float sum = 0.0f;
#pragma unroll
        for (int i = 0; i < 7; i++) {
            int j = lane + 32*i;
            float e = (j < NN) ? __expf(vreg[i] - mx) : 0.0f;
            vreg[i] = e;
            sum += e;
        }
#pragma unroll
        for (int off = 16; off > 0; off >>= 1)
            sum += __shfl_xor_sync(0xFFFFFFFFu, sum, off);
        float inv = 1.0f / sum;
        __syncwarp();
        __half* Prow = P + (size_t)r*(2*AT_SSTR);
#pragma unroll
        for (int i = 0; i < 7; i++) {
            int j = lane + 32*i;
            if (j < AT_NP) Prow[j] = __float2half_rn(vreg[i] * inv);
        }
    }
    __syncthreads();

    // O = P @ V   (13 m-tiles x 2 n-tiles, 13 k-steps); stage in Qs (reused)
    float* stage = (float*)Qs;
    for (int t = w; t < 26; t += 8) {
        int mt = t >> 1, nt = t & 1;
        wmma::fragment<wmma::accumulator, 16, 16, 16, float> c;
        wmma::fill_fragment(c, 0.0f);
#pragma unroll
        for (int kt = 0; kt < 13; kt++) {
            wmma::fragment<wmma::matrix_a, 16, 16, 16, __half, wmma::row_major> af;
            wmma::fragment<wmma::matrix_b, 16, 16, 16, __half, wmma::row_major> bf;
            wmma::load_matrix_sync(af, P + (size_t)mt*16*(2*AT_SSTR) + kt*16, 2*AT_SSTR);
            wmma::load_matrix_sync(bf, Vs + kt*16*32 + nt*16, 32);
            wmma::mma_sync(c, af, bf, c);
        }
        wmma::store_matrix_sync(stage + w*256, c, 16, wmma::mem_row_major);
        __syncwarp();
#pragma unroll
        for (int q = 0; q < 8; q++) {
            int e  = lane*8 + q;
            int rr = e >> 4;
            int cc = e & 15;
            int row = mt*16 + rr;
            if (row < NN)
                o[((size_t)(b*NN + row))*CC + h*DD + nt*16 + cc] =
                    __float2half_rn(stage[w*256 + e]);
        }
        __syncwarp();
    }
}

// ---------------- launch ----------------
extern "C" void kernel_launch(void* const* d_in, const int* in_sizes, int n_in,
                              void* d_out, int out_size)
{
    const float* x      = (const float*)d_in[0];
    const float* W_qkv  = (const float*)d_in[1];
    const float* b_qkv  = (const float*)d_in[2];
    const float* W_proj = (const float*)d_in[3];
    const float* b_proj = (const float*)d_in[4];
    const float* W1     = (const float*)d_in[5];
    const float* b1     = (const float*)d_in[6];
    const float* W2     = (const float*)d_in[7];
    const float* b2     = (const float*)d_in[8];
    const float* sa_w   = (const float*)d_in[9];
    const float* sa_b   = (const float*)d_in[10];
    const float* alpha1 = (const float*)d_in[11];
    const float* gamma1 = (const float*)d_in[12];
    const float* beta1  = (const float*)d_in[13];
    const float* rm1    = (const float*)d_in[14];
    const float* rv1    = (const float*)d_in[15];
    const float* alpha2 = (const float*)d_in[16];
    const float* gamma2 = (const float*)d_in[17];
    const float* beta2  = (const float*)d_in[18];
    const float* rm2    = (const float*)d_in[19];
    const float* rv2    = (const float*)d_in[20];
    float* out = (float*)d_out;

    float *t_p, *t2_p, *t3_p;
    __half *th_p, *qkvh_p, *oh_p, *t2h_p, *hh_p, *wh_p;
    cudaGetSymbolAddress((void**)&t_p,    g_t);
    cudaGetSymbolAddress((void**)&th_p,   g_th);
    cudaGetSymbolAddress((void**)&qkvh_p, g_qkvh);
    cudaGetSymbolAddress((void**)&oh_p,   g_oh);
    cudaGetSymbolAddress((void**)&t2_p,   g_t2);
    cudaGetSymbolAddress((void**)&t2h_p,  g_t2h);
    cudaGetSymbolAddress((void**)&hh_p,   g_hh);
    cudaGetSymbolAddress((void**)&t3_p,   g_t3);
    cudaGetSymbolAddress((void**)&wh_p,   g_wh);

    cudaFuncSetAttribute(gemm_h<0>, cudaFuncAttributeMaxDynamicSharedMemorySize, GEMM_SMEM_BYTES);
    cudaFuncSetAttribute(gemm_h<1>, cudaFuncAttributeMaxDynamicSharedMemorySize, GEMM_SMEM_BYTES);
    cudaFuncSetAttribute(gemm_h<2>, cudaFuncAttributeMaxDynamicSharedMemorySize, GEMM_SMEM_BYTES);
    cudaFuncSetAttribute(gemm_h<3>, cudaFuncAttributeMaxDynamicSharedMemorySize, GEMM_SMEM_BYTES);
    cudaFuncSetAttribute(attn_tc,   cudaFuncAttributeMaxDynamicSharedMemorySize, AT_SMEM_BYTES);

    dim3 tb(32, 8);
    dim3 tg(7, 8, BB);

    // 1) all weight conversions in one launch
    f2h_all<<<1280, 256>>>(W_qkv, W_proj, W1, W2, wh_p);

    // 2) x -> t (f32 + fp16)
    transpose_in<<<tg, tb>>>(x, t_p, th_p);

    // 3) qkv GEMM (fp16 scatter epilogue)
    {
        EpiParams p{};
        p.bias = b_qkv; p.outh = qkvh_p;
        gemm_h<0><<<dim3(768/128, MROWS/128), 128, GEMM_SMEM_BYTES>>>(th_p, wh_p + WQKV_H_OFF, MROWS, 768, CC, p);
    }

    // 4) tensor-core attention (fp16 in/out, f32 softmax)
    attn_tc<<<BB*NH, 256, AT_SMEM_BYTES>>>(qkvh_p, oh_p);

    // 5) proj + residual + repbn1 (f32 + fp16 out)
    {
        EpiParams p{};
        p.bias = b_proj; p.resid = t_p;
        p.gamma = gamma1; p.beta = beta1; p.rm = rm1; p.rv = rv1; p.alpha = alpha1;
        p.out = t2_p; p.outh = t2h_p;
        gemm_h<1><<<dim3(CC/128, MROWS/128), 128, GEMM_SMEM_BYTES>>>(oh_p, wh_p + WPROJ_H_OFF, MROWS, CC, CC, p);
    }

    // 6) FFN up + SpatialSILU (fp16 out)  <- ncu capture slot (6th launch)
    {
        EpiParams p{};
        p.bias = b1; p.saw = sa_w; p.sab = sa_b; p.outh = hh_p;
        gemm_h<2><<<dim3(CM/128, MROWS/128), 128, GEMM_SMEM_BYTES>>>(t2h_p, wh_p + W1_H_OFF, MROWS, CM, CC, p);
    }

    // 7) FFN down + residual + repbn2 (f32 out)
    {
        EpiParams p{};
        p.bias = b2; p.resid = t2_p;
        p.gamma = gamma2; p.beta = beta2; p.rm = rm2; p.rv = rv2; p.alpha = alpha2;
        p.out = t3_p;
        gemm_h<3><<<dim3(CC/128, MROWS/128), 128, GEMM_SMEM_BYTES>>>(hh_p, wh_p + W2_H_OFF, MROWS, CC, CM, p);
    }

    // 8) t3 -> out
    transpose_out<<<tg, tb>>>(t3_p, out);
}

// round 13
// speedup vs baseline: 1.7426x; 1.0133x over previous
#include <cuda_runtime.h>
#include <cuda_fp16.h>
#include <mma.h>
#include <math.h>
#include <cstdint>

using namespace nvcuda;

// ---------------- problem constants ----------------
#define BB   256      // batch
#define CC   256      // channels
#define NN   196      // tokens (14*14)
#define NH   8        // heads
#define DD   32       // head dim
#define CM   2048     // ffn hidden
#define MROWS (BB*NN) // 50176
#define EPSBN 1e-5f

// ---------------- scratch (device globals; no allocations allowed) ----------------
__device__ float  g_t  [(size_t)MROWS*CC];        // tokens [B*N, C] f32 (resid for EPI1)
__device__ __half g_th [(size_t)MROWS*CC];        // tokens fp16 (qkv GEMM input)
__device__ __half g_qkvh[(size_t)3*BB*NH*NN*DD];  // [part, b, h, n, d] fp16
__device__ __half g_oh [(size_t)MROWS*CC];        // attention out fp16 (proj input)
__device__ float  g_t2 [(size_t)MROWS*CC];        // after repbn1 f32 (resid for EPI3)
__device__ __half g_t2h[(size_t)MROWS*CC];        // after repbn1 fp16 (ffn1 input)
__device__ __half g_hh [(size_t)MROWS*CM];        // ffn hidden fp16 (ffn2 input)
__device__ float  g_t3 [(size_t)MROWS*CC];        // before final transpose
__device__ __half g_wh [(size_t)(768*256 + 256*256 + 256*2048 + 2048*256)]; // fp16 weights

#define WQKV_H_OFF  0
#define WPROJ_H_OFF (768*256)
#define W1_H_OFF    (WPROJ_H_OFF + 256*256)
#define W2_H_OFF    (W1_H_OFF + 256*2048)

// ---------------- cp.async helpers ----------------
__device__ __forceinline__ void cp_async16(void* smem_dst, const void* gsrc)
{
    unsigned int s = (unsigned int)__cvta_generic_to_shared(smem_dst);
    asm volatile("cp.async.cg.shared.global [%0], [%1], 16;\n" :: "r"(s), "l"(gsrc));
}
__device__ __forceinline__ void cp_commit() { asm volatile("cp.async.commit_group;\n"); }
template <int N>
__device__ __forceinline__ void cp_wait() { asm volatile("cp.async.wait_group %0;\n" :: "n"(N)); }

// ---------------- single f32->fp16 conversion over all 4 weight tensors ----------------
__global__ void f2h_all(const float* __restrict__ w_qkv, const float* __restrict__ w_proj,
                        const float* __restrict__ w1, const float* __restrict__ w2,
                        __half* __restrict__ dst)
{
    int i = blockIdx.x * 256 + threadIdx.x;
    if (i >= 327680) return;
    const float* src; int off;
    if      (i < 49152)  { src = w_qkv;  off = 0; }
    else if (i < 65536)  { src = w_proj; off = 49152; }
    else if (i < 196608) { src = w1;     off = 65536; }
    else                 { src = w2;     off = 196608; }
    float4 v = ((const float4*)src)[i - off];
    __half2* o2 = (__half2*)dst;
    o2[i*2 + 0] = __floats2half2_rn(v.x, v.y);
    o2[i*2 + 1] = __floats2half2_rn(v.z, v.w);
}

// ---------------- transposes ----------------
__global__ void transpose_in(const float* __restrict__ x, float* __restrict__ t,
                             __half* __restrict__ th)
{
    __shared__ float tile[32][33];
    int b  = blockIdx.z;
    int n0 = blockIdx.x * 32;
    int c0 = blockIdx.y * 32;
    int tx = threadIdx.x, ty = threadIdx.y;
#pragma unroll
    for (int i = 0; i < 4; i++) {
        int c = c0 + ty + 8*i;
        int n = n0 + tx;
        if (n < NN) tile[ty + 8*i][tx] = x[((size_t)b*CC + c)*NN + n];
    }
    __syncthreads();
#pragma unroll
    for (int i = 0; i < 4; i++) {
        int n = n0 + ty + 8*i;
        int c = c0 + tx;
        if (n < NN) {
            float v = tile[tx][ty + 8*i];
            size_t idx = ((size_t)b*NN + n)*CC + c;
            t[idx]  = v;
            th[idx] = __float2half_rn(v);
        }
    }
}

__global__ void transpose_out(const float* __restrict__ t, float* __restrict__ x)
{
    __shared__ float tile[32][33];
    int b  = blockIdx.z;
    int n0 = blockIdx.x * 32;
    int c0 = blockIdx.y * 32;
    int tx = threadIdx.x, ty = threadIdx.y;
#pragma unroll
    for (int i = 0; i < 4; i++) {
        int n = n0 + ty + 8*i;
        int c = c0 + tx;
        if (n < NN) tile[ty + 8*i][tx] = t[((size_t)b*NN + n)*CC + c];
    }
    __syncthreads();
#pragma unroll
    for (int i = 0; i < 4; i++) {
        int c = c0 + ty + 8*i;
        int n = n0 + tx;
        if (n < NN) x[((size_t)b*CC + c)*NN + n] = tile[tx][ty + 8*i];
    }
}

// ---------------- epilogue params ----------------
struct EpiParams {
    const float* bias;
    const float* resid;
    const float* gamma;
    const float* beta;
    const float* rm;
    const float* rv;
    const float* alpha;  // scalar
    const float* saw;    // [B]
    const float* sab;    // [B]
    float*       out;
    __half*      outh;
};

template <int EPI>
__device__ __forceinline__ void apply_epi(int r, int c, float val, const EpiParams& p)
{
    if constexpr (EPI == 0) {
        val += p.bias[c];
        int part = c >> 8;
        int cc   = c & 255;
        int head = cc >> 5;
        int d    = cc & 31;
        int b    = r / NN;
        int n    = r - b * NN;
        size_t PS = (size_t)BB*NH*NN*DD;
        p.outh[(size_t)part*PS + (((size_t)(b*NH + head))*NN + n)*DD + d] = __float2half_rn(val);
    } else if constexpr (EPI == 1) {
        val += p.bias[c];
        float tv = p.resid[(size_t)r*CC + c];
        float s  = p.gamma[c] * rsqrtf(p.rv[c] + EPSBN);
        float a  = p.alpha[0];
        float u  = tv + val;
        float res = u * (s + a) + (p.beta[c] - p.rm[c]*s);
        p.out [(size_t)r*CC + c] = res;
        p.outh[(size_t)r*CC + c] = __float2half_rn(res);
    } else if constexpr (EPI == 3) {
        val += p.bias[c];
        float tv = p.resid[(size_t)r*CC + c];
        float s  = p.gamma[c] * rsqrtf(p.rv[c] + EPSBN);
        float a  = p.alpha[0];
        float u  = tv + val;
        p.out[(size_t)r*CC + c] = u * (s + a) + (p.beta[c] - p.rm[c]*s);
    } else { // EPI == 2
        val += p.bias[c];
        int b = r / NN;
        float w  = p.saw[b];
        float sb = p.sab[b];
        float wg = w * val + sb;
        float sg = 1.0f / (1.0f + __expf(-wg * val));
        p.outh[(size_t)r*CM + c] = __float2half_rn(val * sg);
    }
}

// ---------------- FP16 tiled GEMM, cp.async 2-stage, 64x64 warp tiles ----------------
#define AH_STRIDE 72
#define BH_STRIDE 136
#define AH_BYTES (128*AH_STRIDE*2)
#define BH_BYTES (64*BH_STRIDE*2)
#define GEMM_SMEM_BYTES (2*AH_BYTES + 2*BH_BYTES + 4*256*4)

template <int EPI>
__global__ __launch_bounds__(128, 2)
void gemm_h(const __half* __restrict__ A, const __half* __restrict__ Bm,
            int M, int N, int K, EpiParams p)
{
    extern __shared__ char dynsm[];
    __half* Ah  = (__half*)dynsm;
    __half* Bh  = (__half*)(dynsm + 2*AH_BYTES);
    float*  stg = (float*)(dynsm + 2*AH_BYTES + 2*BH_BYTES);

    int tid  = threadIdx.x;
    int warp = tid >> 5;
    int lane = tid & 31;
    int wm   = warp >> 1;
    int wn   = warp & 1;
    int bn   = blockIdx.x;
    int bm   = blockIdx.y;
    size_t arow0 = (size_t)bm * 128;

    wmma::fragment<wmma::accumulator, 16, 16, 16, float> acc[4][4];
#pragma unroll
    for (int i = 0; i < 4; i++)
#pragma unroll
        for (int j = 0; j < 4; j++)
            wmma::fill_fragment(acc[i][j], 0.0f);

    const __half* Abase = A + arow0 * (size_t)K;
    const __half* Bbase = Bm + (size_t)bn * 128;

    auto load_tile = [&](int stage, int k0) {
        __half* Ad = Ah + stage * (AH_BYTES/2);
        __half* Bd = Bh + stage * (BH_BYTES/2);
#pragma unroll
        for (int i = 0; i < 8; i++) {
            int id  = tid + i * 128;
            int row = id >> 3;
            int c8  = (id & 7) * 8;
            cp_async16(&Ad[row*AH_STRIDE + c8], &Abase[(size_t)row*K + k0 + c8]);
        }
#pragma unroll
        for (int i = 0; i < 8; i++) {
            int id  = tid + i * 128;
            int row = id >> 4;
            int c8  = (id & 15) * 8;
            cp_async16(&Bd[row*BH_STRIDE + c8], &Bbase[(size_t)(k0 + row)*N + c8]);
        }
        cp_commit();
    };

    int ntiles = K >> 6;
    load_tile(0, 0);

    for (int t = 0; t < ntiles; t++) {
        int cur = t & 1;
        if (t + 1 < ntiles) {
            load_tile((t + 1) & 1, (t + 1) << 6);
            cp_wait<1>();
        } else {
            cp_wait<0>();
        }
        __syncthreads();

        __half* Ac = Ah + cur * (AH_BYTES/2);
        __half* Bc = Bh + cur * (BH_BYTES/2);
#pragma unroll
        for (int kk = 0; kk < 64; kk += 16) {
            wmma::fragment<wmma::matrix_a, 16, 16, 16, __half, wmma::row_major> af[4];
            wmma::fragment<wmma::matrix_b, 16, 16, 16, __half, wmma::row_major> bf[4];
#pragma unroll
            for (int i = 0; i < 4; i++)
                wmma::load_matrix_sync(af[i], &Ac[(wm*64 + i*16)*AH_STRIDE + kk], AH_STRIDE);
#pragma unroll
            for (int j = 0; j < 4; j++)
                wmma::load_matrix_sync(bf[j], &Bc[kk*BH_STRIDE + wn*64 + j*16], BH_STRIDE);
#pragma unroll
            for (int i = 0; i < 4; i++)
#pragma unroll
                for (int j = 0; j < 4; j++)
                    wmma::mma_sync(acc[i][j], af[i], bf[j], acc[i][j]);
        }
        __syncthreads();
    }

    float* stw = stg + warp * 256;
#pragma unroll
    for (int i = 0; i < 4; i++) {
#pragma unroll
        for (int j = 0; j < 4; j++) {
            wmma::store_matrix_sync(stw, acc[i][j], 16, wmma::mem_row_major);
            __syncwarp();
            int r0 = bm*128 + wm*64 + i*16;
            int c0 = bn*128 + wn*64 + j*16;
#pragma unroll
            for (int q = 0; q < 8; q++) {
                int e  = lane*8 + q;
                int rr = e >> 4;
                int cc = e & 15;
                apply_epi<EPI>(r0 + rr, c0 + cc, stw[e], p);
            }
            __syncwarp();
        }
    }
}

// ---------------- tensor-core attention: one block per (b, head), 512 threads ----------------
// smem: Qs/Ks/Vs fp16 [208][32] + S f32 [208][216]
#define AT_NP   208
#define AT_SSTR 216
#define AT_QKV_BYTES (AT_NP*32*2)        // 13312
#define AT_SMEM_BYTES (3*AT_QKV_BYTES + AT_NP*AT_SSTR*4)  // 219648
#define AT_WARPS 16

__global__ __launch_bounds__(512)
void attn_tc(const __half* __restrict__ qkv, __half* __restrict__ o)
{
    extern __shared__ char smc[];
    __half* Qs = (__half*)smc;
    __half* Ks = (__half*)(smc + AT_QKV_BYTES);
    __half* Vs = (__half*)(smc + 2*AT_QKV_BYTES);
    float*  S  = (float*)(smc + 3*AT_QKV_BYTES);

    int bh = blockIdx.x;
    int b  = bh >> 3;
    int h  = bh & 7;
    int tid  = threadIdx.x;
    int w    = tid >> 5;
    int lane = tid & 31;

    size_t PS = (size_t)BB*NH*NN*DD;
    const __half* qp = qkv + (size_t)bh*NN*DD;
    const __half* kp = qp + PS;
    const __half* vp = qp + 2*PS;

    // load Q,K,V with zero padding to 208 rows
    const __half hz = __float2half(0.0f);
    for (int idx = tid; idx < AT_NP*DD; idx += 512) {
        int row = idx >> 5;
        __half q = hz, k = hz, v = hz;
        if (row < NN) { q = qp[idx]; k = kp[idx]; v = vp[idx]; }
        Qs[idx] = q; Ks[idx] = k; Vs[idx] = v;
    }
    __syncthreads();

    // S = Q @ K^T   (13x13 tiles of m16n16k16, 2 k-steps)
    for (int t = w; t < 169; t += AT_WARPS) {
        int mt = t / 13, nt = t - mt*13;
        wmma::fragment<wmma::accumulator, 16, 16, 16, float> c;
        wmma::fill_fragment(c, 0.0f);
#pragma unroll
        for (int k0 = 0; k0 < 32; k0 += 16) {
            wmma::fragment<wmma::matrix_a, 16, 16, 16, __half, wmma::row_major> af;
            wmma::fragment<wmma::matrix_b, 16, 16, 16, __half, wmma::col_major> bf;
            wmma::load_matrix_sync(af, Qs + (mt*16)*32 + k0, 32);
            wmma::load_matrix_sync(bf, Ks + (nt*16)*32 + k0, 32);
            wmma::mma_sync(c, af, bf, c);
        }
        wmma::store_matrix_sync(&S[(size_t)mt*16*AT_SSTR + nt*16], c, AT_SSTR, wmma::mem_row_major);
    }
    __syncthreads();

    // softmax rows (f32), write P as fp16 in place (stride 2*AT_SSTR halves)
    const float scale = 0.1767766952966369f;
    __half* P = (__half*)S;
    for (int r = w; r < AT_NP; r += AT_WARPS) {
        float* Srow = S + (size_t)r*AT_SSTR;
        float vreg[7];
#pragma unroll
        for (int i = 0; i < 7; i++) {
            int j = lane + 32*i;
            vreg[i] = (j < NN) ? Srow[j]*scale : -INFINITY;
        }
        float mx = -INFINITY;
#pragma unroll
        for (int i = 0; i < 7; i++) mx = fmaxf(mx, vreg[i]);
#pragma unroll
        for (int off = 16; off > 0; off >>= 1)
            mx = fmaxf(mx, __shfl_xor_sync(0xFFFFFFFFu, mx, off));
        float sum = 0.0f;
#pragma unroll
        for (int i = 0; i < 7; i++) {
            int j = lane + 32*i;
            float e = (j < NN) ? __expf(vreg[i] - mx) : 0.0f;
            vreg[i] = e;
            sum += e;
        }
#pragma unroll
        for (int off = 16; off > 0; off >>= 1)
            sum += __shfl_xor_sync(0xFFFFFFFFu, sum, off);
        float inv = 1.0f / sum;
        __syncwarp();
        __half* Prow = P + (size_t)r*(2*AT_SSTR);
#pragma unroll
        for (int i = 0; i < 7; i++) {
            int j = lane + 32*i;
            if (j < AT_NP) Prow[j] = __float2half_rn(vreg[i] * inv);
        }
    }
    __syncthreads();

    // O = P @ V   (13 m-tiles x 2 n-tiles, 13 k-steps); stage in Qs+Ks (both dead)
    float* stage = (float*)Qs;   // 16 warps x 256 f32 = 16KB <= 26KB (Qs+Ks)
    for (int t = w; t < 26; t += AT_WARPS) {
        int mt = t >> 1, nt = t & 1;
        wmma::fragment<wmma::accumulator, 16, 16, 16, float> c;
        wmma::fill_fragment(c, 0.0f);
#pragma unroll
        for (int kt = 0; kt < 13; kt++) {
            wmma::fragment<wmma::matrix_a, 16, 16, 16, __half, wmma::row_major> af;
            wmma::fragment<wmma::matrix_b, 16, 16, 16, __half, wmma::row_major> bf;
            wmma::load_matrix_sync(af, P + (size_t)mt*16*(2*AT_SSTR) + kt*16, 2*AT_SSTR);
            wmma::load_matrix_sync(bf, Vs + kt*16*32 + nt*16, 32);
            wmma::mma_sync(c, af, bf, c);
        }
        wmma::store_matrix_sync(stage + w*256, c, 16, wmma::mem_row_major);
        __syncwarp();
#pragma unroll
        for (int q = 0; q < 8; q++) {
            int e  = lane*8 + q;
            int rr = e >> 4;
            int cc = e & 15;
            int row = mt*16 + rr;
            if (row < NN)
                o[((size_t)(b*NN + row))*CC + h*DD + nt*16 + cc] =
                    __float2half_rn(stage[w*256 + e]);
        }
        __syncwarp();
    }
}

// ---------------- launch ----------------
extern "C" void kernel_launch(void* const* d_in, const int* in_sizes, int n_in,
                              void* d_out, int out_size)
{
    const float* x      = (const float*)d_in[0];
    const float* W_qkv  = (const float*)d_in[1];
    const float* b_qkv  = (const float*)d_in[2];
    const float* W_proj = (const float*)d_in[3];
    const float* b_proj = (const float*)d_in[4];
    const float* W1     = (const float*)d_in[5];
    const float* b1     = (const float*)d_in[6];
    const float* W2     = (const float*)d_in[7];
    const float* b2     = (const float*)d_in[8];
    const float* sa_w   = (const float*)d_in[9];
    const float* sa_b   = (const float*)d_in[10];
    const float* alpha1 = (const float*)d_in[11];
    const float* gamma1 = (const float*)d_in[12];
    const float* beta1  = (const float*)d_in[13];
    const float* rm1    = (const float*)d_in[14];
    const float* rv1    = (const float*)d_in[15];
    const float* alpha2 = (const float*)d_in[16];
    const float* gamma2 = (const float*)d_in[17];
    const float* beta2  = (const float*)d_in[18];
    const float* rm2    = (const float*)d_in[19];
    const float* rv2    = (const float*)d_in[20];
    float* out = (float*)d_out;

    float *t_p, *t2_p, *t3_p;
    __half *th_p, *qkvh_p, *oh_p, *t2h_p, *hh_p, *wh_p;
    cudaGetSymbolAddress((void**)&t_p,    g_t);
    cudaGetSymbolAddress((void**)&th_p,   g_th);
    cudaGetSymbolAddress((void**)&qkvh_p, g_qkvh);
    cudaGetSymbolAddress((void**)&oh_p,   g_oh);
    cudaGetSymbolAddress((void**)&t2_p,   g_t2);
    cudaGetSymbolAddress((void**)&t2h_p,  g_t2h);
    cudaGetSymbolAddress((void**)&hh_p,   g_hh);
    cudaGetSymbolAddress((void**)&t3_p,   g_t3);
    cudaGetSymbolAddress((void**)&wh_p,   g_wh);

    cudaFuncSetAttribute(gemm_h<0>, cudaFuncAttributeMaxDynamicSharedMemorySize, GEMM_SMEM_BYTES);
    cudaFuncSetAttribute(gemm_h<1>, cudaFuncAttributeMaxDynamicSharedMemorySize, GEMM_SMEM_BYTES);
    cudaFuncSetAttribute(gemm_h<2>, cudaFuncAttributeMaxDynamicSharedMemorySize, GEMM_SMEM_BYTES);
    cudaFuncSetAttribute(gemm_h<3>, cudaFuncAttributeMaxDynamicSharedMemorySize, GEMM_SMEM_BYTES);
    cudaFuncSetAttribute(attn_tc,   cudaFuncAttributeMaxDynamicSharedMemorySize, AT_SMEM_BYTES);

    dim3 tb(32, 8);
    dim3 tg(7, 8, BB);

    // 1) all weight conversions in one launch
    f2h_all<<<1280, 256>>>(W_qkv, W_proj, W1, W2, wh_p);

    // 2) x -> t (f32 + fp16)
    transpose_in<<<tg, tb>>>(x, t_p, th_p);

    // 3) qkv GEMM (fp16 scatter epilogue)
    {
        EpiParams p{};
        p.bias = b_qkv; p.outh = qkvh_p;
        gemm_h<0><<<dim3(768/128, MROWS/128), 128, GEMM_SMEM_BYTES>>>(th_p, wh_p + WQKV_H_OFF, MROWS, 768, CC, p);
    }

    // 4) tensor-core attention (512 threads)
    attn_tc<<<BB*NH, 512, AT_SMEM_BYTES>>>(qkvh_p, oh_p);

    // 5) proj + residual + repbn1 (f32 + fp16 out)
    {
        EpiParams p{};
        p.bias = b_proj; p.resid = t_p;
        p.gamma = gamma1; p.beta = beta1; p.rm = rm1; p.rv = rv1; p.alpha = alpha1;
        p.out = t2_p; p.outh = t2h_p;
        gemm_h<1><<<dim3(CC/128, MROWS/128), 128, GEMM_SMEM_BYTES>>>(oh_p, wh_p + WPROJ_H_OFF, MROWS, CC, CC, p);
    }

    // 6) FFN up + SpatialSILU (fp16 out)
    {
        EpiParams p{};
        p.bias = b1; p.saw = sa_w; p.sab = sa_b; p.outh = hh_p;
        gemm_h<2><<<dim3(CM/128, MROWS/128), 128, GEMM_SMEM_BYTES>>>(t2h_p, wh_p + W1_H_OFF, MROWS, CM, CC, p);
    }

    // 7) FFN down + residual + repbn2 (f32 out)
    {
        EpiParams p{};
        p.bias = b2; p.resid = t2_p;
        p.gamma = gamma2; p.beta = beta2; p.rm = rm2; p.rv = rv2; p.alpha = alpha2;
        p.out = t3_p;
        gemm_h<3><<<dim3(CC/128, MROWS/128), 128, GEMM_SMEM_BYTES>>>(hh_p, wh_p + W2_H_OFF, MROWS, CC, CM, p);
    }

    // 8) t3 -> out
    transpose_out<<<tg, tb>>>(t3_p, out);
}